// round 8
// baseline (speedup 1.0000x reference)
#include <cuda_runtime.h>
#include <cuda_fp16.h>
#include <math.h>
#include <stdint.h>

#define BATCH 2
#define NSEQ  2048
#define DIM   1024
#define HEADS 16
#define DHEAD 64
#define INNER 1024
#define ROWS  (BATCH*NSEQ)   // 4096
#define QKVW  (3*INNER)      // 3072
#define ATT_SCALE 8.0f
#define LN_EPS 1e-5f

// Scratch (static device allocations — allowed)
__device__ __half g_xn_h  [(size_t)ROWS * DIM  ];
__device__ float  g_qkv   [(size_t)ROWS * QKVW ];
__device__ __half g_oat_h [(size_t)ROWS * INNER];
__device__ __half g_wqkvT [(size_t)QKVW * DIM  ];
__device__ __half g_woutT [(size_t)INNER * DIM ];

// ===========================================================================
// helpers
// ===========================================================================
__device__ __forceinline__ void mma_f16(
    float& c0, float& c1, float& c2, float& c3,
    uint32_t a0, uint32_t a1, uint32_t a2, uint32_t a3,
    uint32_t b0, uint32_t b1)
{
    asm volatile(
        "mma.sync.aligned.m16n8k16.row.col.f32.f16.f16.f32 "
        "{%0,%1,%2,%3}, {%4,%5,%6,%7}, {%8,%9}, {%0,%1,%2,%3};"
        : "+f"(c0), "+f"(c1), "+f"(c2), "+f"(c3)
        : "r"(a0), "r"(a1), "r"(a2), "r"(a3), "r"(b0), "r"(b1));
}
__device__ __forceinline__ void ldsm_x4(
    uint32_t& r0, uint32_t& r1, uint32_t& r2, uint32_t& r3, uint32_t addr)
{
    asm volatile("ldmatrix.sync.aligned.m8n8.x4.shared.b16 {%0,%1,%2,%3}, [%4];"
                 : "=r"(r0), "=r"(r1), "=r"(r2), "=r"(r3) : "r"(addr));
}
__device__ __forceinline__ uint32_t pack_h2(float a, float b) {
    __half2 h = __floats2half2_rn(a, b);
    return *(uint32_t*)&h;
}
__device__ __forceinline__ void cp_async16(uint32_t dst, const void* src) {
    asm volatile("cp.async.cg.shared.global [%0], [%1], 16;" :: "r"(dst), "l"(src));
}
__device__ __forceinline__ void cp_commit() {
    asm volatile("cp.async.commit_group;" ::: "memory");
}
__device__ __forceinline__ void cp_wait1() {
    asm volatile("cp.async.wait_group 1;" ::: "memory");
}

// ===========================================================================
// LayerNorm: one block (256 thr) per row of 1024. Output in fp16.
// ===========================================================================
__global__ __launch_bounds__(256) void ln_kernel(
    const float* __restrict__ x, const float* __restrict__ w,
    const float* __restrict__ b, __half* __restrict__ out)
{
    int row = blockIdx.x;
    int tid = threadIdx.x;
    const float4 v = ((const float4*)(x + (size_t)row * DIM))[tid];
    float s  = v.x + v.y + v.z + v.w;
    float ss = v.x*v.x + v.y*v.y + v.z*v.z + v.w*v.w;
    #pragma unroll
    for (int o = 16; o; o >>= 1) {
        s  += __shfl_xor_sync(0xffffffffu, s,  o);
        ss += __shfl_xor_sync(0xffffffffu, ss, o);
    }
    __shared__ float sh_s[8], sh_ss[8];
    int wid = tid >> 5, lane = tid & 31;
    if (lane == 0) { sh_s[wid] = s; sh_ss[wid] = ss; }
    __syncthreads();
    if (tid == 0) {
        float a = 0.f, q = 0.f;
        #pragma unroll
        for (int i = 0; i < 8; i++) { a += sh_s[i]; q += sh_ss[i]; }
        sh_s[0] = a; sh_ss[0] = q;
    }
    __syncthreads();
    float mu   = sh_s[0]  * (1.0f / DIM);
    float var  = sh_ss[0] * (1.0f / DIM) - mu * mu;
    float rstd = rsqrtf(var + LN_EPS);
    float4 w4 = ((const float4*)w)[tid];
    float4 b4 = ((const float4*)b)[tid];
    uint2 o2;
    o2.x = pack_h2((v.x - mu) * rstd * w4.x + b4.x,
                   (v.y - mu) * rstd * w4.y + b4.y);
    o2.y = pack_h2((v.z - mu) * rstd * w4.z + b4.z,
                   (v.w - mu) * rstd * w4.w + b4.w);
    ((uint2*)(out + (size_t)row * DIM))[tid] = o2;
}

// ===========================================================================
// 32x32 smem transpose, fp32 in -> fp16 out
// ===========================================================================
__global__ __launch_bounds__(256) void transpose_kernel(
    const float* __restrict__ in, __half* __restrict__ out, int R, int C)
{
    __shared__ float t[32][33];
    int c0 = blockIdx.x << 5, r0 = blockIdx.y << 5;
    int tx = threadIdx.x & 31, ty = threadIdx.x >> 5;
    #pragma unroll
    for (int i = 0; i < 4; i++) {
        int r = ty + i * 8;
        t[r][tx] = in[(size_t)(r0 + r) * C + c0 + tx];
    }
    __syncthreads();
    #pragma unroll
    for (int i = 0; i < 4; i++) {
        int r = ty + i * 8;
        out[(size_t)(c0 + r) * R + r0 + tx] = __float2half_rn(t[tx][r]);
    }
}

// ===========================================================================
// fp16 mma.sync GEMM v3: ldmatrix fragments + 3-stage cp.async pipeline.
// C[M,N] = A[M,K] @ Bt[N,K]^T, fp32 accumulate.
// CTA tile 128x128, BK=32, 256 threads (8 warps 2m x 4n), 2 CTAs/SM.
// ===========================================================================
#define HKC 32
#define HSTR 40   // smem row stride in halves (80B: LDSM phase covers all banks)

__global__ __launch_bounds__(256, 2) void gemm_fp16_kernel(
    const __half* __restrict__ A, const __half* __restrict__ Bt,
    float* __restrict__ C, int M, int N, int K)
{
    __shared__ __align__(16) __half As[3][128 * HSTR];
    __shared__ __align__(16) __half Bs[3][128 * HSTR];

    const int tid  = threadIdx.x;
    const int wid  = tid >> 5;
    const int lane = tid & 31;
    const int bx = blockIdx.x, by = blockIdx.y;
    const int wm = wid & 1;
    const int wn = wid >> 1;
    const int lt = lane & 3;
    const int l16  = lane & 15;
    const int lkhi = (lane >> 4) << 3;

    const __half* Ab = A  + (size_t)(by * 128) * K;
    const __half* Bb = Bt + (size_t)(bx * 128) * K;

    uint32_t sA[3], sB[3];
    #pragma unroll
    for (int i = 0; i < 3; i++) {
        sA[i] = (uint32_t)__cvta_generic_to_shared(&As[i][0]);
        sB[i] = (uint32_t)__cvta_generic_to_shared(&Bs[i][0]);
    }

    float acc[4][4][4];
    #pragma unroll
    for (int i = 0; i < 4; i++)
        #pragma unroll
        for (int j = 0; j < 4; j++)
            #pragma unroll
            for (int q = 0; q < 4; q++) acc[i][j][q] = 0.f;

    const int NC = K / HKC;
    const int cr  = tid >> 2;        // copy row 0..63 (x2 reps -> 128)
    const int cseg = (tid & 3) << 3; // copy k-offset in halves

    // prologue: chunks 0,1 -> slots 0,1
    #pragma unroll
    for (int st = 0; st < 2; st++) {
        #pragma unroll
        for (int rep = 0; rep < 2; rep++) {
            int r = cr + rep * 64;
            int koff = st * HKC + cseg;
            cp_async16(sA[st] + (uint32_t)(r * HSTR + cseg) * 2, Ab + (size_t)r * K + koff);
            cp_async16(sB[st] + (uint32_t)(r * HSTR + cseg) * 2, Bb + (size_t)r * K + koff);
        }
        cp_commit();
    }

    for (int c = 0; c < NC; c++) {
        cp_wait1();           // stage c resident (all but newest group done)
        __syncthreads();

        if (c + 2 < NC) {
            int slot = (c + 2) % 3;
            #pragma unroll
            for (int rep = 0; rep < 2; rep++) {
                int r = cr + rep * 64;
                int koff = (c + 2) * HKC + cseg;
                cp_async16(sA[slot] + (uint32_t)(r * HSTR + cseg) * 2, Ab + (size_t)r * K + koff);
                cp_async16(sB[slot] + (uint32_t)(r * HSTR + cseg) * 2, Bb + (size_t)r * K + koff);
            }
            cp_commit();
        } else {
            cp_commit();      // empty group keeps wait_group accounting exact
        }

        uint32_t sAc = sA[c % 3], sBc = sB[c % 3];
        #pragma unroll
        for (int ks = 0; ks < 2; ks++) {
            int kk = ks * 16 + lkhi;
            uint32_t a[4][4];
            #pragma unroll
            for (int mi = 0; mi < 4; mi++) {
                int r = wm * 64 + mi * 16 + l16;
                ldsm_x4(a[mi][0], a[mi][1], a[mi][2], a[mi][3],
                        sAc + (uint32_t)(r * HSTR + kk) * 2);
            }
            uint32_t b[4][2];
            #pragma unroll
            for (int np = 0; np < 2; np++) {
                int nr = wn * 32 + np * 16 + l16;
                ldsm_x4(b[2*np][0], b[2*np+1][0], b[2*np][1], b[2*np+1][1],
                        sBc + (uint32_t)(nr * HSTR + kk) * 2);
            }
            #pragma unroll
            for (int ni = 0; ni < 4; ni++)
                #pragma unroll
                for (int mi = 0; mi < 4; mi++)
                    mma_f16(acc[mi][ni][0], acc[mi][ni][1], acc[mi][ni][2], acc[mi][ni][3],
                            a[mi][0], a[mi][1], a[mi][2], a[mi][3], b[ni][0], b[ni][1]);
        }
    }

    const int lg = lane >> 2;
    #pragma unroll
    for (int mi = 0; mi < 4; mi++) {
        int row = by * 128 + wm * 64 + mi * 16 + lg;
        #pragma unroll
        for (int ni = 0; ni < 4; ni++) {
            int col = bx * 128 + wn * 32 + ni * 8 + (lt << 1);
            float2 lo = make_float2(acc[mi][ni][0], acc[mi][ni][1]);
            float2 hi = make_float2(acc[mi][ni][2], acc[mi][ni][3]);
            *(float2*)(C + (size_t)row * N + col)       = lo;
            *(float2*)(C + (size_t)(row + 8) * N + col) = hi;
        }
    }
}

// ===========================================================================
// L2-normalize q and k head-vectors in-place (fp32). One warp per vector.
// ===========================================================================
__global__ __launch_bounds__(256) void l2norm_kernel(float* __restrict__ qkv)
{
    int warp = (blockIdx.x << 3) + (threadIdx.x >> 5);
    int lane = threadIdx.x & 31;
    int row  = warp >> 5;
    int rem  = warp & 31;
    float* base = qkv + (size_t)row * QKVW + (size_t)(rem >> 4) * INNER + (size_t)(rem & 15) * DHEAD;
    float x0 = base[lane];
    float x1 = base[lane + 32];
    float ss = x0*x0 + x1*x1;
    #pragma unroll
    for (int o = 16; o; o >>= 1) ss += __shfl_xor_sync(0xffffffffu, ss, o);
    float inv = 1.0f / fmaxf(sqrtf(ss), 1e-12f);
    base[lane]      = x0 * inv;
    base[lane + 32] = x1 * inv;
}

// ===========================================================================
// Tensor-core flash attention v5 (fp16 mma + ldmatrix fragments)
// CTA: 128 q rows, 256 threads (8 warps x 16 rows). Key tiles of 64.
// Smem (half): Ks[64 key][72], Vt[64 d][72], Ps[128 row][72]  = 36864 B.
// ===========================================================================
#define PH 72
#define ATT5_SMEM ((64 + 64 + 128) * PH * 2)

__global__ __launch_bounds__(256) void attn_tc_kernel(
    const float* __restrict__ qkv, __half* __restrict__ oat)
{
    extern __shared__ __align__(16) __half smh[];
    __half* Ks = smh;              // [key][d]   (B operand, scores)
    __half* Vt = smh + 64 * PH;    // [d][key]   (B operand, PV)
    __half* Ps = smh + 128 * PH;   // [row][key] (A operand, PV)

    const int tid  = threadIdx.x;
    const int w    = tid >> 5;
    const int lane = tid & 31;
    const int lg = lane >> 2, lt = lane & 3;
    const int l16  = lane & 15;
    const int lkhi = (lane >> 4) << 3;
    const int qtIdx = gridDim.x - 1 - blockIdx.x;   // long CTAs first
    const int h = blockIdx.y, bb = blockIdx.z;
    const int row0 = qtIdx * 128;
    const size_t rowbase = (size_t)bb * NSEQ;
    const int R0 = row0 + w * 16;

    const uint32_t sKs = (uint32_t)__cvta_generic_to_shared(Ks);
    const uint32_t sVt = (uint32_t)__cvta_generic_to_shared(Vt);
    const uint32_t sPs = (uint32_t)__cvta_generic_to_shared(Ps);

    // --- Q fragments (prescaled, fp16 packed), resident all kernel ---
    uint32_t aq[4][4];
    {
        const float* q0 = qkv + (rowbase + R0 + lg) * QKVW + h * DHEAD;
        const float* q1 = q0 + 8 * QKVW;
        #pragma unroll
        for (int ks = 0; ks < 4; ks++) {
            int c = ks * 16 + 2 * lt;
            aq[ks][0] = pack_h2(q0[c]     * ATT_SCALE, q0[c + 1] * ATT_SCALE);
            aq[ks][1] = pack_h2(q1[c]     * ATT_SCALE, q1[c + 1] * ATT_SCALE);
            aq[ks][2] = pack_h2(q0[c + 8] * ATT_SCALE, q0[c + 9] * ATT_SCALE);
            aq[ks][3] = pack_h2(q1[c + 8] * ATT_SCALE, q1[c + 9] * ATT_SCALE);
        }
    }

    float oacc[8][4];
    #pragma unroll
    for (int ni = 0; ni < 8; ni++)
        #pragma unroll
        for (int q = 0; q < 4; q++) oacc[ni][q] = 0.f;
    float m0 = -INFINITY, m1 = -INFINITY, l0 = 0.f, l1 = 0.f;

    const int ntiles = 2 * qtIdx + 2;
    for (int jt = 0; jt < ntiles; jt++) {
        const int j0 = jt * 64;
        __syncthreads();   // previous tile's smem reads done

        // --- K/V tiles: fp32 load -> fp16 smem ---
        #pragma unroll
        for (int rep = 0; rep < 4; rep++) {
            int e  = rep * 256 + tid;     // 0..1023
            int i  = e >> 4;              // key 0..63
            int d0 = (e & 15) << 2;       // d 0..60
            const float* src = qkv + (rowbase + j0 + i) * QKVW + INNER + h * DHEAD + d0;
            float4 k4 = *(const float4*)src;
            uint2 kh;
            kh.x = pack_h2(k4.x, k4.y);
            kh.y = pack_h2(k4.z, k4.w);
            *(uint2*)&Ks[i * PH + d0] = kh;
            float4 v4 = *(const float4*)(src + INNER);
            Vt[(d0 + 0) * PH + i] = __float2half_rn(v4.x);
            Vt[(d0 + 1) * PH + i] = __float2half_rn(v4.y);
            Vt[(d0 + 2) * PH + i] = __float2half_rn(v4.z);
            Vt[(d0 + 3) * PH + i] = __float2half_rn(v4.w);
        }
        __syncthreads();

        // warps whose rows all precede this key tile are fully masked: skip
        if (j0 > R0 + 15) continue;

        // --- scores: 16 rows x 64 keys per warp (LDSM B fragments) ---
        float sacc[8][4];
        #pragma unroll
        for (int ni = 0; ni < 8; ni++)
            #pragma unroll
            for (int q = 0; q < 4; q++) sacc[ni][q] = 0.f;

        #pragma unroll
        for (int ks = 0; ks < 4; ks++) {
            int kk = ks * 16 + lkhi;
            #pragma unroll
            for (int np = 0; np < 4; np++) {
                int key = np * 16 + l16;
                uint32_t b0e, b0o, b1e, b1o;
                ldsm_x4(b0e, b0o, b1e, b1o, sKs + (uint32_t)(key * PH + kk) * 2);
                mma_f16(sacc[2*np][0], sacc[2*np][1], sacc[2*np][2], sacc[2*np][3],
                        aq[ks][0], aq[ks][1], aq[ks][2], aq[ks][3], b0e, b1e);
                mma_f16(sacc[2*np+1][0], sacc[2*np+1][1], sacc[2*np+1][2], sacc[2*np+1][3],
                        aq[ks][0], aq[ks][1], aq[ks][2], aq[ks][3], b0o, b1o);
            }
        }

        // --- causal mask (diagonal-crossing tiles only) ---
        if (j0 + 63 > R0) {
            int ra = R0 + lg, rb = ra + 8;
            #pragma unroll
            for (int ni = 0; ni < 8; ni++) {
                int k0c = j0 + ni * 8 + 2 * lt;
                if (k0c     > ra) sacc[ni][0] = -INFINITY;
                if (k0c + 1 > ra) sacc[ni][1] = -INFINITY;
                if (k0c     > rb) sacc[ni][2] = -INFINITY;
                if (k0c + 1 > rb) sacc[ni][3] = -INFINITY;
            }
        }

        // --- online softmax (rows lg and lg+8) ---
        float mt0 = -INFINITY, mt1 = -INFINITY;
        #pragma unroll
        for (int ni = 0; ni < 8; ni++) {
            mt0 = fmaxf(mt0, fmaxf(sacc[ni][0], sacc[ni][1]));
            mt1 = fmaxf(mt1, fmaxf(sacc[ni][2], sacc[ni][3]));
        }
        mt0 = fmaxf(mt0, __shfl_xor_sync(0xffffffffu, mt0, 1));
        mt0 = fmaxf(mt0, __shfl_xor_sync(0xffffffffu, mt0, 2));
        mt1 = fmaxf(mt1, __shfl_xor_sync(0xffffffffu, mt1, 1));
        mt1 = fmaxf(mt1, __shfl_xor_sync(0xffffffffu, mt1, 2));
        float mn0 = fmaxf(m0, mt0), mn1 = fmaxf(m1, mt1);
        float c0f = __expf(m0 - mn0), c1f = __expf(m1 - mn1);
        m0 = mn0; m1 = mn1;

        float s0 = 0.f, s1 = 0.f;
        int rowa = w * 16 + lg;
        #pragma unroll
        for (int ni = 0; ni < 8; ni++) {
            __half2 h01 = __floats2half2_rn(__expf(sacc[ni][0] - m0), __expf(sacc[ni][1] - m0));
            __half2 h23 = __floats2half2_rn(__expf(sacc[ni][2] - m1), __expf(sacc[ni][3] - m1));
            float2 f01 = __half22float2(h01);
            float2 f23 = __half22float2(h23);
            s0 += f01.x + f01.y;
            s1 += f23.x + f23.y;
            int col = ni * 8 + 2 * lt;
            *(uint32_t*)&Ps[rowa * PH + col]       = *(uint32_t*)&h01;
            *(uint32_t*)&Ps[(rowa + 8) * PH + col] = *(uint32_t*)&h23;
        }
        s0 += __shfl_xor_sync(0xffffffffu, s0, 1);
        s0 += __shfl_xor_sync(0xffffffffu, s0, 2);
        s1 += __shfl_xor_sync(0xffffffffu, s1, 1);
        s1 += __shfl_xor_sync(0xffffffffu, s1, 2);
        l0 = l0 * c0f + s0;
        l1 = l1 * c1f + s1;
        #pragma unroll
        for (int ni = 0; ni < 8; ni++) {
            oacc[ni][0] *= c0f; oacc[ni][1] *= c0f;
            oacc[ni][2] *= c1f; oacc[ni][3] *= c1f;
        }
        __syncwarp();

        // --- PV: oacc += P @ V (LDSM A from Ps, LDSM B from Vt) ---
        #pragma unroll
        for (int kc = 0; kc < 4; kc++) {
            int kk = kc * 16 + lkhi;
            uint32_t a0, a1, a2, a3;
            ldsm_x4(a0, a1, a2, a3,
                    sPs + (uint32_t)((w * 16 + l16) * PH + kk) * 2);
            #pragma unroll
            for (int np = 0; np < 4; np++) {
                int dr = np * 16 + l16;
                uint32_t b0e, b0o, b1e, b1o;
                ldsm_x4(b0e, b0o, b1e, b1o, sVt + (uint32_t)(dr * PH + kk) * 2);
                mma_f16(oacc[2*np][0], oacc[2*np][1], oacc[2*np][2], oacc[2*np][3],
                        a0, a1, a2, a3, b0e, b1e);
                mma_f16(oacc[2*np+1][0], oacc[2*np+1][1], oacc[2*np+1][2], oacc[2*np+1][3],
                        a0, a1, a2, a3, b0o, b1o);
            }
        }
    }

    // --- epilogue: normalize, write fp16 [b, n, h*d] ---
    float il0 = 1.0f / l0, il1 = 1.0f / l1;
    __half* outa = oat + (rowbase + R0 + lg) * INNER + h * DHEAD;
    __half* outb = outa + 8 * INNER;
    #pragma unroll
    for (int ni = 0; ni < 8; ni++) {
        int col = ni * 8 + 2 * lt;
        *(uint32_t*)&outa[col] = pack_h2(oacc[ni][0] * il0, oacc[ni][1] * il0);
        *(uint32_t*)&outb[col] = pack_h2(oacc[ni][2] * il1, oacc[ni][3] * il1);
    }
}

// ===========================================================================
extern "C" void kernel_launch(void* const* d_in, const int* in_sizes, int n_in,
                              void* d_out, int out_size)
{
    const float* x    = (const float*)d_in[0];
    const float* lnw  = (const float*)d_in[1];
    const float* lnb  = (const float*)d_in[2];
    const float* Wqkv = (const float*)d_in[3];
    const float* Wout = (const float*)d_in[4];
    float* out = (float*)d_out;

    __half *xn, *oath, *wqkvT, *woutT;
    float *qkvp;
    cudaGetSymbolAddress((void**)&xn,    g_xn_h);
    cudaGetSymbolAddress((void**)&qkvp,  g_qkv);
    cudaGetSymbolAddress((void**)&oath,  g_oat_h);
    cudaGetSymbolAddress((void**)&wqkvT, g_wqkvT);
    cudaGetSymbolAddress((void**)&woutT, g_woutT);

    cudaFuncSetAttribute(attn_tc_kernel, cudaFuncAttributeMaxDynamicSharedMemorySize, ATT5_SMEM);

    ln_kernel<<<ROWS, 256>>>(x, lnw, lnb, xn);

    transpose_kernel<<<dim3(QKVW / 32, DIM / 32), 256>>>(Wqkv, wqkvT, DIM, QKVW);
    transpose_kernel<<<dim3(INNER / 32, DIM / 32), 256>>>(Wout, woutT, DIM, INNER);

    gemm_fp16_kernel<<<dim3(QKVW / 128, ROWS / 128), 256>>>(
        xn, wqkvT, qkvp, ROWS, QKVW, DIM);

    l2norm_kernel<<<(ROWS * HEADS * 2) / 8, 256>>>(qkvp);

    attn_tc_kernel<<<dim3(NSEQ / 128, HEADS, BATCH), 256, ATT5_SMEM>>>(qkvp, oath);

    gemm_fp16_kernel<<<dim3(INNER / 128, ROWS / 128), 256>>>(
        oath, woutT, out, ROWS, INNER, DIM);
}

// round 9
// speedup vs baseline: 1.2873x; 1.2873x over previous
#include <cuda_runtime.h>
#include <cuda_fp16.h>
#include <math.h>
#include <stdint.h>

#define BATCH 2
#define NSEQ  2048
#define DIM   1024
#define HEADS 16
#define DHEAD 64
#define INNER 1024
#define ROWS  (BATCH*NSEQ)   // 4096
#define QKVW  (3*INNER)      // 3072
#define LN_EPS 1e-5f

// Scratch (static device allocations — allowed)
__device__ __half g_xn_h  [(size_t)ROWS * DIM  ];
__device__ __half g_qkv_h [(size_t)ROWS * QKVW ];
__device__ __half g_oat_h [(size_t)ROWS * INNER];
__device__ __half g_wqkvT [(size_t)QKVW * DIM  ];
__device__ __half g_woutT [(size_t)INNER * DIM ];

// ===========================================================================
// helpers
// ===========================================================================
__device__ __forceinline__ void mma_f16(
    float& c0, float& c1, float& c2, float& c3,
    uint32_t a0, uint32_t a1, uint32_t a2, uint32_t a3,
    uint32_t b0, uint32_t b1)
{
    asm volatile(
        "mma.sync.aligned.m16n8k16.row.col.f32.f16.f16.f32 "
        "{%0,%1,%2,%3}, {%4,%5,%6,%7}, {%8,%9}, {%0,%1,%2,%3};"
        : "+f"(c0), "+f"(c1), "+f"(c2), "+f"(c3)
        : "r"(a0), "r"(a1), "r"(a2), "r"(a3), "r"(b0), "r"(b1));
}
__device__ __forceinline__ void ldsm_x4(
    uint32_t& r0, uint32_t& r1, uint32_t& r2, uint32_t& r3, uint32_t addr)
{
    asm volatile("ldmatrix.sync.aligned.m8n8.x4.shared.b16 {%0,%1,%2,%3}, [%4];"
                 : "=r"(r0), "=r"(r1), "=r"(r2), "=r"(r3) : "r"(addr));
}
__device__ __forceinline__ void ldsm_x4_t(
    uint32_t& r0, uint32_t& r1, uint32_t& r2, uint32_t& r3, uint32_t addr)
{
    asm volatile("ldmatrix.sync.aligned.m8n8.x4.trans.shared.b16 {%0,%1,%2,%3}, [%4];"
                 : "=r"(r0), "=r"(r1), "=r"(r2), "=r"(r3) : "r"(addr));
}
__device__ __forceinline__ uint32_t pack_h2(float a, float b) {
    __half2 h = __floats2half2_rn(a, b);
    return *(uint32_t*)&h;
}
__device__ __forceinline__ void cp_async16(uint32_t dst, const void* src) {
    asm volatile("cp.async.cg.shared.global [%0], [%1], 16;" :: "r"(dst), "l"(src));
}
__device__ __forceinline__ void cp_commit() {
    asm volatile("cp.async.commit_group;" ::: "memory");
}
__device__ __forceinline__ void cp_wait0() {
    asm volatile("cp.async.wait_group 0;" ::: "memory");
}
__device__ __forceinline__ void cp_wait1() {
    asm volatile("cp.async.wait_group 1;" ::: "memory");
}

// ===========================================================================
// LayerNorm: one block (256 thr) per row of 1024. fp16 out.
// ===========================================================================
__global__ __launch_bounds__(256) void ln_kernel(
    const float* __restrict__ x, const float* __restrict__ w,
    const float* __restrict__ b, __half* __restrict__ out)
{
    int row = blockIdx.x;
    int tid = threadIdx.x;
    const float4 v = ((const float4*)(x + (size_t)row * DIM))[tid];
    float s  = v.x + v.y + v.z + v.w;
    float ss = v.x*v.x + v.y*v.y + v.z*v.z + v.w*v.w;
    #pragma unroll
    for (int o = 16; o; o >>= 1) {
        s  += __shfl_xor_sync(0xffffffffu, s,  o);
        ss += __shfl_xor_sync(0xffffffffu, ss, o);
    }
    __shared__ float sh_s[8], sh_ss[8];
    int wid = tid >> 5, lane = tid & 31;
    if (lane == 0) { sh_s[wid] = s; sh_ss[wid] = ss; }
    __syncthreads();
    if (tid == 0) {
        float a = 0.f, q = 0.f;
        #pragma unroll
        for (int i = 0; i < 8; i++) { a += sh_s[i]; q += sh_ss[i]; }
        sh_s[0] = a; sh_ss[0] = q;
    }
    __syncthreads();
    float mu   = sh_s[0]  * (1.0f / DIM);
    float var  = sh_ss[0] * (1.0f / DIM) - mu * mu;
    float rstd = rsqrtf(var + LN_EPS);
    float4 w4 = ((const float4*)w)[tid];
    float4 b4 = ((const float4*)b)[tid];
    uint2 o2;
    o2.x = pack_h2((v.x - mu) * rstd * w4.x + b4.x,
                   (v.y - mu) * rstd * w4.y + b4.y);
    o2.y = pack_h2((v.z - mu) * rstd * w4.z + b4.z,
                   (v.w - mu) * rstd * w4.w + b4.w);
    ((uint2*)(out + (size_t)row * DIM))[tid] = o2;
}

// ===========================================================================
// 32x32 smem transpose, fp32 in -> fp16 out
// ===========================================================================
__global__ __launch_bounds__(256) void transpose_kernel(
    const float* __restrict__ in, __half* __restrict__ out, int R, int C)
{
    __shared__ float t[32][33];
    int c0 = blockIdx.x << 5, r0 = blockIdx.y << 5;
    int tx = threadIdx.x & 31, ty = threadIdx.x >> 5;
    #pragma unroll
    for (int i = 0; i < 4; i++) {
        int r = ty + i * 8;
        t[r][tx] = in[(size_t)(r0 + r) * C + c0 + tx];
    }
    __syncthreads();
    #pragma unroll
    for (int i = 0; i < 4; i++) {
        int r = ty + i * 8;
        out[(size_t)(c0 + r) * R + r0 + tx] = __float2half_rn(t[tx][r]);
    }
}

// ===========================================================================
// fp16 mma GEMM, 2-stage cp.async + ldmatrix.
// MODE 0: C fp32 (Cf).  MODE 1: C fp16 (Ch), and for bx<16 (q,k tiles)
// each 64-col head vector is l2-normalized in the epilogue.
// CTA tile 128x128, BK=32, 256 threads (8 warps 2m x 4n).
// ===========================================================================
#define HKC 32
#define HSTR 40

template<int MODE>
__global__ __launch_bounds__(256, 2) void gemm_fp16_kernel(
    const __half* __restrict__ A, const __half* __restrict__ Bt,
    float* __restrict__ Cf, __half* __restrict__ Ch, int M, int N, int K)
{
    __shared__ __align__(16) __half As[2][128 * HSTR];
    __shared__ __align__(16) __half Bs[2][128 * HSTR];

    const int tid  = threadIdx.x;
    const int wid  = tid >> 5;
    const int lane = tid & 31;
    const int bx = blockIdx.x, by = blockIdx.y;
    const int wm = wid & 1;
    const int wn = wid >> 1;
    const int lg = lane >> 2;
    const int lt = lane & 3;
    const int l16  = lane & 15;
    const int lkhi = (lane >> 4) << 3;

    const __half* Ab = A  + (size_t)(by * 128) * K;
    const __half* Bb = Bt + (size_t)(bx * 128) * K;

    uint32_t sA[2], sB[2];
    sA[0] = (uint32_t)__cvta_generic_to_shared(&As[0][0]);
    sA[1] = (uint32_t)__cvta_generic_to_shared(&As[1][0]);
    sB[0] = (uint32_t)__cvta_generic_to_shared(&Bs[0][0]);
    sB[1] = (uint32_t)__cvta_generic_to_shared(&Bs[1][0]);

    float acc[4][4][4];
    #pragma unroll
    for (int i = 0; i < 4; i++)
        #pragma unroll
        for (int j = 0; j < 4; j++)
            #pragma unroll
            for (int q = 0; q < 4; q++) acc[i][j][q] = 0.f;

    const int NC = K / HKC;
    const int cr   = tid >> 2;        // copy row 0..63 (+64)
    const int cseg = (tid & 3) << 3;  // k-offset in halves

    // prologue: chunk 0 -> slot 0
    #pragma unroll
    for (int rep = 0; rep < 2; rep++) {
        int r = cr + rep * 64;
        cp_async16(sA[0] + (uint32_t)(r * HSTR + cseg) * 2, Ab + (size_t)r * K + cseg);
        cp_async16(sB[0] + (uint32_t)(r * HSTR + cseg) * 2, Bb + (size_t)r * K + cseg);
    }
    cp_commit();

    for (int c = 0; c < NC; c++) {
        cp_wait0();
        __syncthreads();

        if (c + 1 < NC) {
            int slot = (c + 1) & 1;
            int koff = (c + 1) * HKC + cseg;
            #pragma unroll
            for (int rep = 0; rep < 2; rep++) {
                int r = cr + rep * 64;
                cp_async16(sA[slot] + (uint32_t)(r * HSTR + cseg) * 2, Ab + (size_t)r * K + koff);
                cp_async16(sB[slot] + (uint32_t)(r * HSTR + cseg) * 2, Bb + (size_t)r * K + koff);
            }
            cp_commit();
        }

        uint32_t sAc = sA[c & 1], sBc = sB[c & 1];
        #pragma unroll
        for (int ks = 0; ks < 2; ks++) {
            int kk = ks * 16 + lkhi;
            uint32_t a[4][4];
            #pragma unroll
            for (int mi = 0; mi < 4; mi++) {
                int r = wm * 64 + mi * 16 + l16;
                ldsm_x4(a[mi][0], a[mi][1], a[mi][2], a[mi][3],
                        sAc + (uint32_t)(r * HSTR + kk) * 2);
            }
            uint32_t b[4][2];
            #pragma unroll
            for (int np = 0; np < 2; np++) {
                int nr = wn * 32 + np * 16 + l16;
                ldsm_x4(b[2*np][0], b[2*np+1][0], b[2*np][1], b[2*np+1][1],
                        sBc + (uint32_t)(nr * HSTR + kk) * 2);
            }
            #pragma unroll
            for (int ni = 0; ni < 4; ni++)
                #pragma unroll
                for (int mi = 0; mi < 4; mi++)
                    mma_f16(acc[mi][ni][0], acc[mi][ni][1], acc[mi][ni][2], acc[mi][ni][3],
                            a[mi][0], a[mi][1], a[mi][2], a[mi][3], b[ni][0], b[ni][1]);
        }
    }

    if (MODE == 0) {
        #pragma unroll
        for (int mi = 0; mi < 4; mi++) {
            int row = by * 128 + wm * 64 + mi * 16 + lg;
            #pragma unroll
            for (int ni = 0; ni < 4; ni++) {
                int col = bx * 128 + wn * 32 + ni * 8 + (lt << 1);
                *(float2*)(Cf + (size_t)row * N + col)       = make_float2(acc[mi][ni][0], acc[mi][ni][1]);
                *(float2*)(Cf + (size_t)(row + 8) * N + col) = make_float2(acc[mi][ni][2], acc[mi][ni][3]);
            }
        }
    } else {
        // per-row, per-64col-head sum of squares -> l2 normalize q,k tiles
        const bool donorm = (bx < 16);   // bx 0-7: q, 8-15: k, 16-23: v
        __syncthreads();                 // done reading As
        float* red = (float*)&As[0][0];  // [4 wn][128 rows]
        float ssl[4], ssh[4];
        #pragma unroll
        for (int mi = 0; mi < 4; mi++) {
            float a = 0.f, h = 0.f;
            #pragma unroll
            for (int ni = 0; ni < 4; ni++) {
                a += acc[mi][ni][0]*acc[mi][ni][0] + acc[mi][ni][1]*acc[mi][ni][1];
                h += acc[mi][ni][2]*acc[mi][ni][2] + acc[mi][ni][3]*acc[mi][ni][3];
            }
            a += __shfl_xor_sync(0xffffffffu, a, 1);
            a += __shfl_xor_sync(0xffffffffu, a, 2);
            h += __shfl_xor_sync(0xffffffffu, h, 1);
            h += __shfl_xor_sync(0xffffffffu, h, 2);
            ssl[mi] = a; ssh[mi] = h;
        }
        if (lt == 0) {
            #pragma unroll
            for (int mi = 0; mi < 4; mi++) {
                int rl = wm * 64 + mi * 16 + lg;
                red[wn * 128 + rl]     = ssl[mi];
                red[wn * 128 + rl + 8] = ssh[mi];
            }
        }
        __syncthreads();
        #pragma unroll
        for (int mi = 0; mi < 4; mi++) {
            int rl = wm * 64 + mi * 16 + lg;
            float il = 1.f, ih = 1.f;
            if (donorm) {
                float tl = ssl[mi] + red[(wn ^ 1) * 128 + rl];
                float th = ssh[mi] + red[(wn ^ 1) * 128 + rl + 8];
                il = 1.0f / fmaxf(sqrtf(tl), 1e-12f);
                ih = 1.0f / fmaxf(sqrtf(th), 1e-12f);
            }
            int row = by * 128 + rl;
            #pragma unroll
            for (int ni = 0; ni < 4; ni++) {
                int col = bx * 128 + wn * 32 + ni * 8 + (lt << 1);
                *(uint32_t*)(Ch + (size_t)row * N + col) =
                    pack_h2(acc[mi][ni][0] * il, acc[mi][ni][1] * il);
                *(uint32_t*)(Ch + (size_t)(row + 8) * N + col) =
                    pack_h2(acc[mi][ni][2] * ih, acc[mi][ni][3] * ih);
            }
        }
    }
}

// ===========================================================================
// Tensor-core flash attention v6: fp16 qkv, cp.async double-buffered K/V,
// register-resident P (score frags ARE the PV A frags), ldmatrix.trans V.
// CTA: 128 q rows, 256 threads (8 warps x 16 rows). Key tiles of 64.
// ===========================================================================
#define PH 72

__global__ __launch_bounds__(256) void attn_tc_kernel(
    const __half* __restrict__ qkv, __half* __restrict__ oat)
{
    __shared__ __align__(16) __half Ks[2][64 * PH];
    __shared__ __align__(16) __half Vs[2][64 * PH];

    const int tid  = threadIdx.x;
    const int w    = tid >> 5;
    const int lane = tid & 31;
    const int lg = lane >> 2, lt = lane & 3;
    const int l16  = lane & 15;
    const int lkhi = (lane >> 4) << 3;
    const int qtIdx = gridDim.x - 1 - blockIdx.x;   // long CTAs first
    const int h = blockIdx.y, bb = blockIdx.z;
    const int row0 = qtIdx * 128;
    const size_t rowbase = (size_t)bb * NSEQ;
    const int R0 = row0 + w * 16;

    uint32_t sK[2], sV[2];
    sK[0] = (uint32_t)__cvta_generic_to_shared(&Ks[0][0]);
    sK[1] = (uint32_t)__cvta_generic_to_shared(&Ks[1][0]);
    sV[0] = (uint32_t)__cvta_generic_to_shared(&Vs[0][0]);
    sV[1] = (uint32_t)__cvta_generic_to_shared(&Vs[1][0]);

    // --- Q fragments: fp16 loads, exact x8 scale, resident all kernel ---
    uint32_t aq[4][4];
    {
        const __half2 s8 = __floats2half2_rn(8.0f, 8.0f);
        const __half* q0 = qkv + (rowbase + R0 + lg) * QKVW + h * DHEAD;
        const __half* q1 = q0 + 8 * QKVW;
        #pragma unroll
        for (int ks = 0; ks < 4; ks++) {
            int c = ks * 16 + 2 * lt;
            __half2 v;
            v = __hmul2(*(const __half2*)&q0[c], s8);     aq[ks][0] = *(uint32_t*)&v;
            v = __hmul2(*(const __half2*)&q1[c], s8);     aq[ks][1] = *(uint32_t*)&v;
            v = __hmul2(*(const __half2*)&q0[c + 8], s8); aq[ks][2] = *(uint32_t*)&v;
            v = __hmul2(*(const __half2*)&q1[c + 8], s8); aq[ks][3] = *(uint32_t*)&v;
        }
    }

    float oacc[8][4];
    #pragma unroll
    for (int ni = 0; ni < 8; ni++)
        #pragma unroll
        for (int q = 0; q < 4; q++) oacc[ni][q] = 0.f;
    float m0 = -INFINITY, m1 = -INFINITY, l0 = 0.f, l1 = 0.f;

    const int ntiles = 2 * qtIdx + 2;
    const int ci  = tid >> 3;         // kv row 0..31 (x2 reps)
    const int cs8 = (tid & 7) << 3;   // d-offset in halves (16B chunks)

    // prologue: tile 0 -> slot 0
    #pragma unroll
    for (int rep = 0; rep < 2; rep++) {
        int i = ci + rep * 32;
        const __half* src = qkv + (rowbase + i) * QKVW + INNER + h * DHEAD + cs8;
        cp_async16(sK[0] + (uint32_t)(i * PH + cs8) * 2, src);
        cp_async16(sV[0] + (uint32_t)(i * PH + cs8) * 2, src + INNER);
    }
    cp_commit();

    for (int jt = 0; jt < ntiles; jt++) {
        const int j0 = jt * 64;
        // issue next tile into the other slot, then wait for current
        if (jt + 1 < ntiles) {
            int slot = (jt + 1) & 1;
            int jn = (jt + 1) * 64;
            #pragma unroll
            for (int rep = 0; rep < 2; rep++) {
                int i = ci + rep * 32;
                const __half* src = qkv + (rowbase + jn + i) * QKVW + INNER + h * DHEAD + cs8;
                cp_async16(sK[slot] + (uint32_t)(i * PH + cs8) * 2, src);
                cp_async16(sV[slot] + (uint32_t)(i * PH + cs8) * 2, src + INNER);
            }
        }
        cp_commit();
        cp_wait1();
        __syncthreads();

        const int slot = jt & 1;
        if (j0 <= R0 + 15) {
            // --- scores ---
            float sacc[8][4];
            #pragma unroll
            for (int ni = 0; ni < 8; ni++)
                #pragma unroll
                for (int q = 0; q < 4; q++) sacc[ni][q] = 0.f;

            #pragma unroll
            for (int ks = 0; ks < 4; ks++) {
                int kk = ks * 16 + lkhi;
                #pragma unroll
                for (int np = 0; np < 4; np++) {
                    int key = np * 16 + l16;
                    uint32_t b0e, b0o, b1e, b1o;
                    ldsm_x4(b0e, b0o, b1e, b1o, sK[slot] + (uint32_t)(key * PH + kk) * 2);
                    mma_f16(sacc[2*np][0], sacc[2*np][1], sacc[2*np][2], sacc[2*np][3],
                            aq[ks][0], aq[ks][1], aq[ks][2], aq[ks][3], b0e, b1e);
                    mma_f16(sacc[2*np+1][0], sacc[2*np+1][1], sacc[2*np+1][2], sacc[2*np+1][3],
                            aq[ks][0], aq[ks][1], aq[ks][2], aq[ks][3], b0o, b1o);
                }
            }

            // --- causal mask (diagonal-crossing tiles only) ---
            if (j0 + 63 > R0) {
                int ra = R0 + lg, rb = ra + 8;
                #pragma unroll
                for (int ni = 0; ni < 8; ni++) {
                    int k0c = j0 + ni * 8 + 2 * lt;
                    if (k0c     > ra) sacc[ni][0] = -INFINITY;
                    if (k0c + 1 > ra) sacc[ni][1] = -INFINITY;
                    if (k0c     > rb) sacc[ni][2] = -INFINITY;
                    if (k0c + 1 > rb) sacc[ni][3] = -INFINITY;
                }
            }

            // --- online softmax; pack P into A-fragment registers ---
            float mt0 = -INFINITY, mt1 = -INFINITY;
            #pragma unroll
            for (int ni = 0; ni < 8; ni++) {
                mt0 = fmaxf(mt0, fmaxf(sacc[ni][0], sacc[ni][1]));
                mt1 = fmaxf(mt1, fmaxf(sacc[ni][2], sacc[ni][3]));
            }
            mt0 = fmaxf(mt0, __shfl_xor_sync(0xffffffffu, mt0, 1));
            mt0 = fmaxf(mt0, __shfl_xor_sync(0xffffffffu, mt0, 2));
            mt1 = fmaxf(mt1, __shfl_xor_sync(0xffffffffu, mt1, 1));
            mt1 = fmaxf(mt1, __shfl_xor_sync(0xffffffffu, mt1, 2));
            float mn0 = fmaxf(m0, mt0), mn1 = fmaxf(m1, mt1);
            float c0f = __expf(m0 - mn0), c1f = __expf(m1 - mn1);
            m0 = mn0; m1 = mn1;

            float s0 = 0.f, s1 = 0.f;
            uint32_t pa[4][4];
            #pragma unroll
            for (int ni = 0; ni < 8; ni++) {
                __half2 h01 = __floats2half2_rn(__expf(sacc[ni][0] - m0), __expf(sacc[ni][1] - m0));
                __half2 h23 = __floats2half2_rn(__expf(sacc[ni][2] - m1), __expf(sacc[ni][3] - m1));
                float2 f01 = __half22float2(h01);
                float2 f23 = __half22float2(h23);
                s0 += f01.x + f01.y;
                s1 += f23.x + f23.y;
                int kc = ni >> 1;
                if ((ni & 1) == 0) { pa[kc][0] = *(uint32_t*)&h01; pa[kc][1] = *(uint32_t*)&h23; }
                else               { pa[kc][2] = *(uint32_t*)&h01; pa[kc][3] = *(uint32_t*)&h23; }
            }
            s0 += __shfl_xor_sync(0xffffffffu, s0, 1);
            s0 += __shfl_xor_sync(0xffffffffu, s0, 2);
            s1 += __shfl_xor_sync(0xffffffffu, s1, 1);
            s1 += __shfl_xor_sync(0xffffffffu, s1, 2);
            l0 = l0 * c0f + s0;
            l1 = l1 * c1f + s1;
            #pragma unroll
            for (int ni = 0; ni < 8; ni++) {
                oacc[ni][0] *= c0f; oacc[ni][1] *= c0f;
                oacc[ni][2] *= c1f; oacc[ni][3] *= c1f;
            }

            // --- PV: B from Vs[key][d] via ldmatrix.trans ---
            #pragma unroll
            for (int kc = 0; kc < 4; kc++) {
                #pragma unroll
                for (int np = 0; np < 4; np++) {
                    uint32_t r0, r1, r2, r3;
                    ldsm_x4_t(r0, r1, r2, r3,
                              sV[slot] + (uint32_t)((kc * 16 + l16) * PH + np * 16 + lkhi) * 2);
                    mma_f16(oacc[2*np][0], oacc[2*np][1], oacc[2*np][2], oacc[2*np][3],
                            pa[kc][0], pa[kc][1], pa[kc][2], pa[kc][3], r0, r1);
                    mma_f16(oacc[2*np+1][0], oacc[2*np+1][1], oacc[2*np+1][2], oacc[2*np+1][3],
                            pa[kc][0], pa[kc][1], pa[kc][2], pa[kc][3], r2, r3);
                }
            }
        }
        __syncthreads();   // slot may be overwritten by next iteration's cp.async
    }

    // --- epilogue: normalize, write fp16 [b, n, h*d] ---
    float il0 = 1.0f / l0, il1 = 1.0f / l1;
    __half* outa = oat + (rowbase + R0 + lg) * INNER + h * DHEAD;
    __half* outb = outa + 8 * INNER;
    #pragma unroll
    for (int ni = 0; ni < 8; ni++) {
        int col = ni * 8 + 2 * lt;
        *(uint32_t*)&outa[col] = pack_h2(oacc[ni][0] * il0, oacc[ni][1] * il0);
        *(uint32_t*)&outb[col] = pack_h2(oacc[ni][2] * il1, oacc[ni][3] * il1);
    }
}

// ===========================================================================
extern "C" void kernel_launch(void* const* d_in, const int* in_sizes, int n_in,
                              void* d_out, int out_size)
{
    const float* x    = (const float*)d_in[0];
    const float* lnw  = (const float*)d_in[1];
    const float* lnb  = (const float*)d_in[2];
    const float* Wqkv = (const float*)d_in[3];
    const float* Wout = (const float*)d_in[4];
    float* out = (float*)d_out;

    __half *xn, *qkvh, *oath, *wqkvT, *woutT;
    cudaGetSymbolAddress((void**)&xn,    g_xn_h);
    cudaGetSymbolAddress((void**)&qkvh,  g_qkv_h);
    cudaGetSymbolAddress((void**)&oath,  g_oat_h);
    cudaGetSymbolAddress((void**)&wqkvT, g_wqkvT);
    cudaGetSymbolAddress((void**)&woutT, g_woutT);

    ln_kernel<<<ROWS, 256>>>(x, lnw, lnb, xn);

    transpose_kernel<<<dim3(QKVW / 32, DIM / 32), 256>>>(Wqkv, wqkvT, DIM, QKVW);
    transpose_kernel<<<dim3(INNER / 32, DIM / 32), 256>>>(Wout, woutT, DIM, INNER);

    // QKV projection, fused q/k l2-normalization, fp16 out
    gemm_fp16_kernel<1><<<dim3(QKVW / 128, ROWS / 128), 256>>>(
        xn, wqkvT, nullptr, qkvh, ROWS, QKVW, DIM);

    attn_tc_kernel<<<dim3(NSEQ / 128, HEADS, BATCH), 256>>>(qkvh, oath);

    gemm_fp16_kernel<0><<<dim3(INNER / 128, ROWS / 128), 256>>>(
        oath, woutT, out, nullptr, ROWS, INNER, DIM);
}

// round 12
// speedup vs baseline: 1.3528x; 1.0509x over previous
#include <cuda_runtime.h>
#include <cuda_fp16.h>
#include <math.h>
#include <stdint.h>

#define BATCH 2
#define NSEQ  2048
#define DIM   1024
#define HEADS 16
#define DHEAD 64
#define INNER 1024
#define ROWS  (BATCH*NSEQ)   // 4096
#define QKVW  (3*INNER)      // 3072
#define LN_EPS 1e-5f

// Scratch (static device allocations — allowed)
__device__ __half g_xn_h  [(size_t)ROWS * DIM  ];
__device__ __half g_qkv_h [(size_t)ROWS * QKVW ];
__device__ __half g_oat_h [(size_t)ROWS * INNER];
__device__ __half g_wqkvT [(size_t)QKVW * DIM  ];
__device__ __half g_woutT [(size_t)INNER * DIM ];

// ===========================================================================
// helpers
// ===========================================================================
__device__ __forceinline__ void mma_f16(
    float& c0, float& c1, float& c2, float& c3,
    uint32_t a0, uint32_t a1, uint32_t a2, uint32_t a3,
    uint32_t b0, uint32_t b1)
{
    asm volatile(
        "mma.sync.aligned.m16n8k16.row.col.f32.f16.f16.f32 "
        "{%0,%1,%2,%3}, {%4,%5,%6,%7}, {%8,%9}, {%0,%1,%2,%3};"
        : "+f"(c0), "+f"(c1), "+f"(c2), "+f"(c3)
        : "r"(a0), "r"(a1), "r"(a2), "r"(a3), "r"(b0), "r"(b1));
}
__device__ __forceinline__ void ldsm_x4(
    uint32_t& r0, uint32_t& r1, uint32_t& r2, uint32_t& r3, uint32_t addr)
{
    asm volatile("ldmatrix.sync.aligned.m8n8.x4.shared.b16 {%0,%1,%2,%3}, [%4];"
                 : "=r"(r0), "=r"(r1), "=r"(r2), "=r"(r3) : "r"(addr));
}
__device__ __forceinline__ void ldsm_x4_t(
    uint32_t& r0, uint32_t& r1, uint32_t& r2, uint32_t& r3, uint32_t addr)
{
    asm volatile("ldmatrix.sync.aligned.m8n8.x4.trans.shared.b16 {%0,%1,%2,%3}, [%4];"
                 : "=r"(r0), "=r"(r1), "=r"(r2), "=r"(r3) : "r"(addr));
}
__device__ __forceinline__ uint32_t pack_h2(float a, float b) {
    __half2 h = __floats2half2_rn(a, b);
    return *(uint32_t*)&h;
}
__device__ __forceinline__ void cp_async16(uint32_t dst, const void* src) {
    asm volatile("cp.async.cg.shared.global [%0], [%1], 16;" :: "r"(dst), "l"(src));
}
__device__ __forceinline__ void cp_commit() {
    asm volatile("cp.async.commit_group;" ::: "memory");
}
__device__ __forceinline__ void cp_wait0() {
    asm volatile("cp.async.wait_group 0;" ::: "memory");
}
__device__ __forceinline__ void cp_wait1() {
    asm volatile("cp.async.wait_group 1;" ::: "memory");
}

// ===========================================================================
// LayerNorm: one block (256 thr) per row of 1024. fp16 out.
// ===========================================================================
__global__ __launch_bounds__(256) void ln_kernel(
    const float* __restrict__ x, const float* __restrict__ w,
    const float* __restrict__ b, __half* __restrict__ out)
{
    int row = blockIdx.x;
    int tid = threadIdx.x;
    const float4 v = ((const float4*)(x + (size_t)row * DIM))[tid];
    float s  = v.x + v.y + v.z + v.w;
    float ss = v.x*v.x + v.y*v.y + v.z*v.z + v.w*v.w;
    #pragma unroll
    for (int o = 16; o; o >>= 1) {
        s  += __shfl_xor_sync(0xffffffffu, s,  o);
        ss += __shfl_xor_sync(0xffffffffu, ss, o);
    }
    __shared__ float sh_s[8], sh_ss[8];
    int wid = tid >> 5, lane = tid & 31;
    if (lane == 0) { sh_s[wid] = s; sh_ss[wid] = ss; }
    __syncthreads();
    if (tid == 0) {
        float a = 0.f, q = 0.f;
        #pragma unroll
        for (int i = 0; i < 8; i++) { a += sh_s[i]; q += sh_ss[i]; }
        sh_s[0] = a; sh_ss[0] = q;
    }
    __syncthreads();
    float mu   = sh_s[0]  * (1.0f / DIM);
    float var  = sh_ss[0] * (1.0f / DIM) - mu * mu;
    float rstd = rsqrtf(var + LN_EPS);
    float4 w4 = ((const float4*)w)[tid];
    float4 b4 = ((const float4*)b)[tid];
    uint2 o2;
    o2.x = pack_h2((v.x - mu) * rstd * w4.x + b4.x,
                   (v.y - mu) * rstd * w4.y + b4.y);
    o2.y = pack_h2((v.z - mu) * rstd * w4.z + b4.z,
                   (v.w - mu) * rstd * w4.w + b4.w);
    ((uint2*)(out + (size_t)row * DIM))[tid] = o2;
}

// ===========================================================================
// 32x32 smem transpose, fp32 in -> fp16 out
// ===========================================================================
__global__ __launch_bounds__(256) void transpose_kernel(
    const float* __restrict__ in, __half* __restrict__ out, int R, int C)
{
    __shared__ float t[32][33];
    int c0 = blockIdx.x << 5, r0 = blockIdx.y << 5;
    int tx = threadIdx.x & 31, ty = threadIdx.x >> 5;
    #pragma unroll
    for (int i = 0; i < 4; i++) {
        int r = ty + i * 8;
        t[r][tx] = in[(size_t)(r0 + r) * C + c0 + tx];
    }
    __syncthreads();
    #pragma unroll
    for (int i = 0; i < 4; i++) {
        int r = ty + i * 8;
        out[(size_t)(c0 + r) * R + r0 + tx] = __float2half_rn(t[tx][r]);
    }
}

// ===========================================================================
// fp16 mma GEMM v6: BK=64, DYNAMIC smem, array-indexed slots (no XOR —
// XOR-after-add was the R10/R11 crash), ldmatrix + 2-stage cp.async.
// MODE 0: C fp32. MODE 1: C fp16 + fused q/k l2norm (bx<16).
// CTA tile 128x128, 256 threads (8 warps 2m x 4n).
// ===========================================================================
#define HKC 64
#define HSTR 72
#define GEMM_SMEM (4 * 128 * HSTR * 2)   // As0,As1,Bs0,Bs1 = 73728 B

template<int MODE>
__global__ __launch_bounds__(256, 2) void gemm_fp16_kernel(
    const __half* __restrict__ A, const __half* __restrict__ Bt,
    float* __restrict__ Cf, __half* __restrict__ Ch, int M, int N, int K)
{
    extern __shared__ __align__(16) __half gsm[];

    const int tid  = threadIdx.x;
    const int wid  = tid >> 5;
    const int lane = tid & 31;
    const int bx = blockIdx.x, by = blockIdx.y;
    const int wm = wid & 1;
    const int wn = wid >> 1;
    const int lg = lane >> 2;
    const int lt = lane & 3;
    const int l16  = lane & 15;
    const int lkhi = (lane >> 4) << 3;

    uint32_t sA[2], sB[2];
    sA[0] = (uint32_t)__cvta_generic_to_shared(gsm);
    sA[1] = sA[0] + 128 * HSTR * 2;
    sB[0] = sA[0] + 2 * 128 * HSTR * 2;
    sB[1] = sA[0] + 3 * 128 * HSTR * 2;

    float acc[4][4][4];
    #pragma unroll
    for (int i = 0; i < 4; i++)
        #pragma unroll
        for (int j = 0; j < 4; j++)
            #pragma unroll
            for (int q = 0; q < 4; q++) acc[i][j][q] = 0.f;

    const int NC = K / HKC;                 // 16
    const int ci   = tid >> 3;              // copy row 0..31 (x4 reps)
    const int cs8  = (tid & 7) << 3;        // k-offset in halves

    const __half* Asrc = A  + (size_t)(by * 128 + ci) * K + cs8;
    const __half* Bsrc = Bt + (size_t)(bx * 128 + ci) * K + cs8;
    const uint32_t cdst = (uint32_t)(ci * HSTR + cs8) * 2;

    // loop-invariant per-thread ldsm offsets (relative to slot base)
    uint32_t aOff[4], bOff[2];
    #pragma unroll
    for (int mi = 0; mi < 4; mi++)
        aOff[mi] = (uint32_t)((wm * 64 + mi * 16 + l16) * HSTR + lkhi) * 2;
    #pragma unroll
    for (int np = 0; np < 2; np++)
        bOff[np] = (uint32_t)((wn * 32 + np * 16 + l16) * HSTR + lkhi) * 2;

    // prologue: chunk 0 -> slot 0
    #pragma unroll
    for (int rep = 0; rep < 4; rep++) {
        uint32_t d = cdst + (uint32_t)(rep * 32 * HSTR) * 2;
        cp_async16(sA[0] + d, Asrc + (size_t)(rep * 32) * K);
        cp_async16(sB[0] + d, Bsrc + (size_t)(rep * 32) * K);
    }
    cp_commit();
    Asrc += HKC; Bsrc += HKC;

    for (int c = 0; c < NC; c++) {
        cp_wait0();
        __syncthreads();

        if (c + 1 < NC) {
            const int slot = (c + 1) & 1;
            #pragma unroll
            for (int rep = 0; rep < 4; rep++) {
                uint32_t d = cdst + (uint32_t)(rep * 32 * HSTR) * 2;
                cp_async16(sA[slot] + d, Asrc + (size_t)(rep * 32) * K);
                cp_async16(sB[slot] + d, Bsrc + (size_t)(rep * 32) * K);
            }
            cp_commit();
            Asrc += HKC; Bsrc += HKC;
        }

        const uint32_t sAc = sA[c & 1], sBc = sB[c & 1];
        #pragma unroll
        for (int ks = 0; ks < 4; ks++) {
            const uint32_t ko = (uint32_t)(ks * 16) * 2;
            uint32_t a[4][4];
            #pragma unroll
            for (int mi = 0; mi < 4; mi++)
                ldsm_x4(a[mi][0], a[mi][1], a[mi][2], a[mi][3], sAc + aOff[mi] + ko);
            uint32_t b[4][2];
            #pragma unroll
            for (int np = 0; np < 2; np++)
                ldsm_x4(b[2*np][0], b[2*np+1][0], b[2*np][1], b[2*np+1][1], sBc + bOff[np] + ko);
            #pragma unroll
            for (int ni = 0; ni < 4; ni++)
                #pragma unroll
                for (int mi = 0; mi < 4; mi++)
                    mma_f16(acc[mi][ni][0], acc[mi][ni][1], acc[mi][ni][2], acc[mi][ni][3],
                            a[mi][0], a[mi][1], a[mi][2], a[mi][3], b[ni][0], b[ni][1]);
        }
    }

    if (MODE == 0) {
        #pragma unroll
        for (int mi = 0; mi < 4; mi++) {
            int row = by * 128 + wm * 64 + mi * 16 + lg;
            #pragma unroll
            for (int ni = 0; ni < 4; ni++) {
                int col = bx * 128 + wn * 32 + ni * 8 + (lt << 1);
                *(float2*)(Cf + (size_t)row * N + col)       = make_float2(acc[mi][ni][0], acc[mi][ni][1]);
                *(float2*)(Cf + (size_t)(row + 8) * N + col) = make_float2(acc[mi][ni][2], acc[mi][ni][3]);
            }
        }
    } else {
        const bool donorm = (bx < 16);   // bx 0-7: q, 8-15: k, 16-23: v
        __syncthreads();
        float* red = (float*)gsm;        // [4 wn][128 rows]
        float ssl[4], ssh[4];
        #pragma unroll
        for (int mi = 0; mi < 4; mi++) {
            float a = 0.f, h = 0.f;
            #pragma unroll
            for (int ni = 0; ni < 4; ni++) {
                a += acc[mi][ni][0]*acc[mi][ni][0] + acc[mi][ni][1]*acc[mi][ni][1];
                h += acc[mi][ni][2]*acc[mi][ni][2] + acc[mi][ni][3]*acc[mi][ni][3];
            }
            a += __shfl_xor_sync(0xffffffffu, a, 1);
            a += __shfl_xor_sync(0xffffffffu, a, 2);
            h += __shfl_xor_sync(0xffffffffu, h, 1);
            h += __shfl_xor_sync(0xffffffffu, h, 2);
            ssl[mi] = a; ssh[mi] = h;
        }
        if (lt == 0) {
            #pragma unroll
            for (int mi = 0; mi < 4; mi++) {
                int rl = wm * 64 + mi * 16 + lg;
                red[wn * 128 + rl]     = ssl[mi];
                red[wn * 128 + rl + 8] = ssh[mi];
            }
        }
        __syncthreads();
        #pragma unroll
        for (int mi = 0; mi < 4; mi++) {
            int rl = wm * 64 + mi * 16 + lg;
            float il = 1.f, ih = 1.f;
            if (donorm) {
                float tl = ssl[mi] + red[(wn ^ 1) * 128 + rl];
                float th = ssh[mi] + red[(wn ^ 1) * 128 + rl + 8];
                il = 1.0f / fmaxf(sqrtf(tl), 1e-12f);
                ih = 1.0f / fmaxf(sqrtf(th), 1e-12f);
            }
            int row = by * 128 + rl;
            #pragma unroll
            for (int ni = 0; ni < 4; ni++) {
                int col = bx * 128 + wn * 32 + ni * 8 + (lt << 1);
                *(uint32_t*)(Ch + (size_t)row * N + col) =
                    pack_h2(acc[mi][ni][0] * il, acc[mi][ni][1] * il);
                *(uint32_t*)(Ch + (size_t)(row + 8) * N + col) =
                    pack_h2(acc[mi][ni][2] * ih, acc[mi][ni][3] * ih);
            }
        }
    }
}

// ===========================================================================
// Tensor-core flash attention v6 (R9 verbatim — proven): fp16 qkv, cp.async
// double-buffered K/V, register-resident P, ldmatrix.trans V.
// CTA: 128 q rows, 256 threads (8 warps x 16 rows). Key tiles of 64.
// ===========================================================================
#define PH 72

__global__ __launch_bounds__(256) void attn_tc_kernel(
    const __half* __restrict__ qkv, __half* __restrict__ oat)
{
    __shared__ __align__(16) __half Ks[2][64 * PH];
    __shared__ __align__(16) __half Vs[2][64 * PH];

    const int tid  = threadIdx.x;
    const int w    = tid >> 5;
    const int lane = tid & 31;
    const int lg = lane >> 2, lt = lane & 3;
    const int l16  = lane & 15;
    const int lkhi = (lane >> 4) << 3;
    const int qtIdx = gridDim.x - 1 - blockIdx.x;   // long CTAs first
    const int h = blockIdx.y, bb = blockIdx.z;
    const int row0 = qtIdx * 128;
    const size_t rowbase = (size_t)bb * NSEQ;
    const int R0 = row0 + w * 16;

    uint32_t sK[2], sV[2];
    sK[0] = (uint32_t)__cvta_generic_to_shared(&Ks[0][0]);
    sK[1] = (uint32_t)__cvta_generic_to_shared(&Ks[1][0]);
    sV[0] = (uint32_t)__cvta_generic_to_shared(&Vs[0][0]);
    sV[1] = (uint32_t)__cvta_generic_to_shared(&Vs[1][0]);

    // --- Q fragments: fp16 loads, exact x8 scale, resident all kernel ---
    uint32_t aq[4][4];
    {
        const __half2 s8 = __floats2half2_rn(8.0f, 8.0f);
        const __half* q0 = qkv + (rowbase + R0 + lg) * QKVW + h * DHEAD;
        const __half* q1 = q0 + 8 * QKVW;
        #pragma unroll
        for (int ks = 0; ks < 4; ks++) {
            int c = ks * 16 + 2 * lt;
            __half2 v;
            v = __hmul2(*(const __half2*)&q0[c], s8);     aq[ks][0] = *(uint32_t*)&v;
            v = __hmul2(*(const __half2*)&q1[c], s8);     aq[ks][1] = *(uint32_t*)&v;
            v = __hmul2(*(const __half2*)&q0[c + 8], s8); aq[ks][2] = *(uint32_t*)&v;
            v = __hmul2(*(const __half2*)&q1[c + 8], s8); aq[ks][3] = *(uint32_t*)&v;
        }
    }

    float oacc[8][4];
    #pragma unroll
    for (int ni = 0; ni < 8; ni++)
        #pragma unroll
        for (int q = 0; q < 4; q++) oacc[ni][q] = 0.f;
    float m0 = -INFINITY, m1 = -INFINITY, l0 = 0.f, l1 = 0.f;

    const int ntiles = 2 * qtIdx + 2;
    const int ci  = tid >> 3;         // kv row 0..31 (x2 reps)
    const int cs8 = (tid & 7) << 3;   // d-offset in halves

    const __half* kvsrc = qkv + (rowbase + ci) * QKVW + INNER + h * DHEAD + cs8;
    const uint32_t cdst = (uint32_t)(ci * PH + cs8) * 2;

    // prologue: tile 0 -> slot 0
    #pragma unroll
    for (int rep = 0; rep < 2; rep++) {
        const __half* src = kvsrc + (size_t)(rep * 32) * QKVW;
        cp_async16(sK[0] + cdst + (uint32_t)(rep * 32 * PH) * 2, src);
        cp_async16(sV[0] + cdst + (uint32_t)(rep * 32 * PH) * 2, src + INNER);
    }
    cp_commit();
    kvsrc += (size_t)64 * QKVW;

    for (int jt = 0; jt < ntiles; jt++) {
        const int j0 = jt * 64;
        if (jt + 1 < ntiles) {
            const int slot = (jt + 1) & 1;
            #pragma unroll
            for (int rep = 0; rep < 2; rep++) {
                const __half* src = kvsrc + (size_t)(rep * 32) * QKVW;
                cp_async16(sK[slot] + cdst + (uint32_t)(rep * 32 * PH) * 2, src);
                cp_async16(sV[slot] + cdst + (uint32_t)(rep * 32 * PH) * 2, src + INNER);
            }
            kvsrc += (size_t)64 * QKVW;
        }
        cp_commit();
        cp_wait1();
        __syncthreads();

        const int slot = jt & 1;
        if (j0 <= R0 + 15) {
            // --- scores ---
            float sacc[8][4];
            #pragma unroll
            for (int ni = 0; ni < 8; ni++)
                #pragma unroll
                for (int q = 0; q < 4; q++) sacc[ni][q] = 0.f;

            #pragma unroll
            for (int ks = 0; ks < 4; ks++) {
                const uint32_t ko = (uint32_t)(ks * 16) * 2;
                #pragma unroll
                for (int np = 0; np < 4; np++) {
                    uint32_t b0e, b0o, b1e, b1o;
                    ldsm_x4(b0e, b0o, b1e, b1o,
                            sK[slot] + (uint32_t)((np * 16 + l16) * PH + lkhi) * 2 + ko);
                    mma_f16(sacc[2*np][0], sacc[2*np][1], sacc[2*np][2], sacc[2*np][3],
                            aq[ks][0], aq[ks][1], aq[ks][2], aq[ks][3], b0e, b1e);
                    mma_f16(sacc[2*np+1][0], sacc[2*np+1][1], sacc[2*np+1][2], sacc[2*np+1][3],
                            aq[ks][0], aq[ks][1], aq[ks][2], aq[ks][3], b0o, b1o);
                }
            }

            // --- causal mask (diagonal-crossing tiles only) ---
            if (j0 + 63 > R0) {
                int ra = R0 + lg, rb = ra + 8;
                #pragma unroll
                for (int ni = 0; ni < 8; ni++) {
                    int k0c = j0 + ni * 8 + 2 * lt;
                    if (k0c     > ra) sacc[ni][0] = -INFINITY;
                    if (k0c + 1 > ra) sacc[ni][1] = -INFINITY;
                    if (k0c     > rb) sacc[ni][2] = -INFINITY;
                    if (k0c + 1 > rb) sacc[ni][3] = -INFINITY;
                }
            }

            // --- online softmax; pack P into A-fragment registers ---
            float mt0 = -INFINITY, mt1 = -INFINITY;
            #pragma unroll
            for (int ni = 0; ni < 8; ni++) {
                mt0 = fmaxf(mt0, fmaxf(sacc[ni][0], sacc[ni][1]));
                mt1 = fmaxf(mt1, fmaxf(sacc[ni][2], sacc[ni][3]));
            }
            mt0 = fmaxf(mt0, __shfl_xor_sync(0xffffffffu, mt0, 1));
            mt0 = fmaxf(mt0, __shfl_xor_sync(0xffffffffu, mt0, 2));
            mt1 = fmaxf(mt1, __shfl_xor_sync(0xffffffffu, mt1, 1));
            mt1 = fmaxf(mt1, __shfl_xor_sync(0xffffffffu, mt1, 2));
            float mn0 = fmaxf(m0, mt0), mn1 = fmaxf(m1, mt1);
            float c0f = __expf(m0 - mn0), c1f = __expf(m1 - mn1);
            m0 = mn0; m1 = mn1;

            float s0 = 0.f, s1 = 0.f;
            uint32_t pa[4][4];
            #pragma unroll
            for (int ni = 0; ni < 8; ni++) {
                __half2 h01 = __floats2half2_rn(__expf(sacc[ni][0] - m0), __expf(sacc[ni][1] - m0));
                __half2 h23 = __floats2half2_rn(__expf(sacc[ni][2] - m1), __expf(sacc[ni][3] - m1));
                float2 f01 = __half22float2(h01);
                float2 f23 = __half22float2(h23);
                s0 += f01.x + f01.y;
                s1 += f23.x + f23.y;
                int kc = ni >> 1;
                if ((ni & 1) == 0) { pa[kc][0] = *(uint32_t*)&h01; pa[kc][1] = *(uint32_t*)&h23; }
                else               { pa[kc][2] = *(uint32_t*)&h01; pa[kc][3] = *(uint32_t*)&h23; }
            }
            s0 += __shfl_xor_sync(0xffffffffu, s0, 1);
            s0 += __shfl_xor_sync(0xffffffffu, s0, 2);
            s1 += __shfl_xor_sync(0xffffffffu, s1, 1);
            s1 += __shfl_xor_sync(0xffffffffu, s1, 2);
            l0 = l0 * c0f + s0;
            l1 = l1 * c1f + s1;
            #pragma unroll
            for (int ni = 0; ni < 8; ni++) {
                oacc[ni][0] *= c0f; oacc[ni][1] *= c0f;
                oacc[ni][2] *= c1f; oacc[ni][3] *= c1f;
            }

            // --- PV: B from Vs[key][d] via ldmatrix.trans ---
            #pragma unroll
            for (int kc = 0; kc < 4; kc++) {
                #pragma unroll
                for (int np = 0; np < 4; np++) {
                    uint32_t r0, r1, r2, r3;
                    ldsm_x4_t(r0, r1, r2, r3,
                              sV[slot] + (uint32_t)((kc * 16 + l16) * PH + np * 16 + lkhi) * 2);
                    mma_f16(oacc[2*np][0], oacc[2*np][1], oacc[2*np][2], oacc[2*np][3],
                            pa[kc][0], pa[kc][1], pa[kc][2], pa[kc][3], r0, r1);
                    mma_f16(oacc[2*np+1][0], oacc[2*np+1][1], oacc[2*np+1][2], oacc[2*np+1][3],
                            pa[kc][0], pa[kc][1], pa[kc][2], pa[kc][3], r2, r3);
                }
            }
        }
        __syncthreads();   // slot may be overwritten by next iteration's cp.async
    }

    // --- epilogue: normalize, write fp16 [b, n, h*d] ---
    float il0 = 1.0f / l0, il1 = 1.0f / l1;
    __half* outa = oat + (rowbase + R0 + lg) * INNER + h * DHEAD;
    __half* outb = outa + 8 * INNER;
    #pragma unroll
    for (int ni = 0; ni < 8; ni++) {
        int col = ni * 8 + 2 * lt;
        *(uint32_t*)&outa[col] = pack_h2(oacc[ni][0] * il0, oacc[ni][1] * il0);
        *(uint32_t*)&outb[col] = pack_h2(oacc[ni][2] * il1, oacc[ni][3] * il1);
    }
}

// ===========================================================================
extern "C" void kernel_launch(void* const* d_in, const int* in_sizes, int n_in,
                              void* d_out, int out_size)
{
    const float* x    = (const float*)d_in[0];
    const float* lnw  = (const float*)d_in[1];
    const float* lnb  = (const float*)d_in[2];
    const float* Wqkv = (const float*)d_in[3];
    const float* Wout = (const float*)d_in[4];
    float* out = (float*)d_out;

    __half *xn, *qkvh, *oath, *wqkvT, *woutT;
    cudaGetSymbolAddress((void**)&xn,    g_xn_h);
    cudaGetSymbolAddress((void**)&qkvh,  g_qkv_h);
    cudaGetSymbolAddress((void**)&oath,  g_oat_h);
    cudaGetSymbolAddress((void**)&wqkvT, g_wqkvT);
    cudaGetSymbolAddress((void**)&woutT, g_woutT);

    cudaFuncSetAttribute(gemm_fp16_kernel<0>,
                         cudaFuncAttributeMaxDynamicSharedMemorySize, GEMM_SMEM);
    cudaFuncSetAttribute(gemm_fp16_kernel<1>,
                         cudaFuncAttributeMaxDynamicSharedMemorySize, GEMM_SMEM);

    ln_kernel<<<ROWS, 256>>>(x, lnw, lnb, xn);

    transpose_kernel<<<dim3(QKVW / 32, DIM / 32), 256>>>(Wqkv, wqkvT, DIM, QKVW);
    transpose_kernel<<<dim3(INNER / 32, DIM / 32), 256>>>(Wout, woutT, DIM, INNER);

    // QKV projection, fused q/k l2-normalization, fp16 out
    gemm_fp16_kernel<1><<<dim3(QKVW / 128, ROWS / 128), 256, GEMM_SMEM>>>(
        xn, wqkvT, nullptr, qkvh, ROWS, QKVW, DIM);

    attn_tc_kernel<<<dim3(NSEQ / 128, HEADS, BATCH), 256>>>(qkvh, oath);

    gemm_fp16_kernel<0><<<dim3(INNER / 128, ROWS / 128), 256, GEMM_SMEM>>>(
        oath, woutT, out, nullptr, ROWS, INNER, DIM);
}

// round 13
// speedup vs baseline: 1.3690x; 1.0120x over previous
#include <cuda_runtime.h>
#include <cuda_fp16.h>
#include <math.h>
#include <stdint.h>

#define BATCH 2
#define NSEQ  2048
#define DIM   1024
#define HEADS 16
#define DHEAD 64
#define INNER 1024
#define ROWS  (BATCH*NSEQ)   // 4096
#define QKVW  (3*INNER)      // 3072
#define LN_EPS 1e-5f

// Scratch (static device allocations — allowed)
__device__ __half g_xn_h  [(size_t)ROWS * DIM  ];
__device__ __half g_qkv_h [(size_t)ROWS * QKVW ];
__device__ __half g_oat_h [(size_t)ROWS * INNER];
__device__ __half g_wqkvT [(size_t)QKVW * DIM  ];
__device__ __half g_woutT [(size_t)INNER * DIM ];

// ===========================================================================
// helpers
// ===========================================================================
__device__ __forceinline__ void mma_f16(
    float& c0, float& c1, float& c2, float& c3,
    uint32_t a0, uint32_t a1, uint32_t a2, uint32_t a3,
    uint32_t b0, uint32_t b1)
{
    asm volatile(
        "mma.sync.aligned.m16n8k16.row.col.f32.f16.f16.f32 "
        "{%0,%1,%2,%3}, {%4,%5,%6,%7}, {%8,%9}, {%0,%1,%2,%3};"
        : "+f"(c0), "+f"(c1), "+f"(c2), "+f"(c3)
        : "r"(a0), "r"(a1), "r"(a2), "r"(a3), "r"(b0), "r"(b1));
}
__device__ __forceinline__ void ldsm_x4(
    uint32_t& r0, uint32_t& r1, uint32_t& r2, uint32_t& r3, uint32_t addr)
{
    asm volatile("ldmatrix.sync.aligned.m8n8.x4.shared.b16 {%0,%1,%2,%3}, [%4];"
                 : "=r"(r0), "=r"(r1), "=r"(r2), "=r"(r3) : "r"(addr));
}
__device__ __forceinline__ void ldsm_x4_t(
    uint32_t& r0, uint32_t& r1, uint32_t& r2, uint32_t& r3, uint32_t addr)
{
    asm volatile("ldmatrix.sync.aligned.m8n8.x4.trans.shared.b16 {%0,%1,%2,%3}, [%4];"
                 : "=r"(r0), "=r"(r1), "=r"(r2), "=r"(r3) : "r"(addr));
}
__device__ __forceinline__ uint32_t pack_h2(float a, float b) {
    __half2 h = __floats2half2_rn(a, b);
    return *(uint32_t*)&h;
}
__device__ __forceinline__ void cp_async16(uint32_t dst, const void* src) {
    asm volatile("cp.async.cg.shared.global [%0], [%1], 16;" :: "r"(dst), "l"(src));
}
__device__ __forceinline__ void cp_commit() {
    asm volatile("cp.async.commit_group;" ::: "memory");
}
__device__ __forceinline__ void cp_wait0() {
    asm volatile("cp.async.wait_group 0;" ::: "memory");
}
__device__ __forceinline__ void cp_wait1() {
    asm volatile("cp.async.wait_group 1;" ::: "memory");
}

// ===========================================================================
// LayerNorm: one block (256 thr) per row of 1024. fp16 out.
// ===========================================================================
__global__ __launch_bounds__(256) void ln_kernel(
    const float* __restrict__ x, const float* __restrict__ w,
    const float* __restrict__ b, __half* __restrict__ out)
{
    int row = blockIdx.x;
    int tid = threadIdx.x;
    const float4 v = ((const float4*)(x + (size_t)row * DIM))[tid];
    float s  = v.x + v.y + v.z + v.w;
    float ss = v.x*v.x + v.y*v.y + v.z*v.z + v.w*v.w;
    #pragma unroll
    for (int o = 16; o; o >>= 1) {
        s  += __shfl_xor_sync(0xffffffffu, s,  o);
        ss += __shfl_xor_sync(0xffffffffu, ss, o);
    }
    __shared__ float sh_s[8], sh_ss[8];
    int wid = tid >> 5, lane = tid & 31;
    if (lane == 0) { sh_s[wid] = s; sh_ss[wid] = ss; }
    __syncthreads();
    if (tid == 0) {
        float a = 0.f, q = 0.f;
        #pragma unroll
        for (int i = 0; i < 8; i++) { a += sh_s[i]; q += sh_ss[i]; }
        sh_s[0] = a; sh_ss[0] = q;
    }
    __syncthreads();
    float mu   = sh_s[0]  * (1.0f / DIM);
    float var  = sh_ss[0] * (1.0f / DIM) - mu * mu;
    float rstd = rsqrtf(var + LN_EPS);
    float4 w4 = ((const float4*)w)[tid];
    float4 b4 = ((const float4*)b)[tid];
    uint2 o2;
    o2.x = pack_h2((v.x - mu) * rstd * w4.x + b4.x,
                   (v.y - mu) * rstd * w4.y + b4.y);
    o2.y = pack_h2((v.z - mu) * rstd * w4.z + b4.z,
                   (v.w - mu) * rstd * w4.w + b4.w);
    ((uint2*)(out + (size_t)row * DIM))[tid] = o2;
}

// ===========================================================================
// 32x32 smem transpose, fp32 in -> fp16 out
// ===========================================================================
__global__ __launch_bounds__(256) void transpose_kernel(
    const float* __restrict__ in, __half* __restrict__ out, int R, int C)
{
    __shared__ float t[32][33];
    int c0 = blockIdx.x << 5, r0 = blockIdx.y << 5;
    int tx = threadIdx.x & 31, ty = threadIdx.x >> 5;
    #pragma unroll
    for (int i = 0; i < 4; i++) {
        int r = ty + i * 8;
        t[r][tx] = in[(size_t)(r0 + r) * C + c0 + tx];
    }
    __syncthreads();
    #pragma unroll
    for (int i = 0; i < 4; i++) {
        int r = ty + i * 8;
        out[(size_t)(c0 + r) * R + r0 + tx] = __float2half_rn(t[tx][r]);
    }
}

// ===========================================================================
// fp16 mma GEMM v7: CTA tile 128x64 (occupancy-optimized), BK=64, dynamic
// smem 55296 B, 3 CTAs/SM. 256 threads, 8 warps 4m x 2n, warp tile 32x32.
// MODE 0: C fp32. MODE 1: C fp16 + fused q/k l2norm (bx<32; one head/tile).
// ===========================================================================
#define HKC 64
#define HSTR 72
#define GEMM_SMEM ((2*128 + 2*64) * HSTR * 2)   // 55296 B

template<int MODE>
__global__ __launch_bounds__(256, 3) void gemm_fp16_kernel(
    const __half* __restrict__ A, const __half* __restrict__ Bt,
    float* __restrict__ Cf, __half* __restrict__ Ch, int M, int N, int K)
{
    extern __shared__ __align__(16) __half gsm[];

    const int tid  = threadIdx.x;
    const int wid  = tid >> 5;
    const int lane = tid & 31;
    const int bx = blockIdx.x, by = blockIdx.y;
    const int wm = wid & 3;           // 0..3 (m)
    const int wn = wid >> 2;          // 0..1 (n)
    const int lg = lane >> 2;
    const int lt = lane & 3;
    const int l16  = lane & 15;
    const int lkhi = (lane >> 4) << 3;

    uint32_t sA[2], sB[2];
    sA[0] = (uint32_t)__cvta_generic_to_shared(gsm);
    sA[1] = sA[0] + 128 * HSTR * 2;
    sB[0] = sA[0] + 2 * 128 * HSTR * 2;
    sB[1] = sB[0] + 64 * HSTR * 2;

    float acc[2][4][4];
    #pragma unroll
    for (int i = 0; i < 2; i++)
        #pragma unroll
        for (int j = 0; j < 4; j++)
            #pragma unroll
            for (int q = 0; q < 4; q++) acc[i][j][q] = 0.f;

    const int NC = K / HKC;                 // 16
    const int ci   = tid >> 3;              // copy row 0..31
    const int cs8  = (tid & 7) << 3;        // k-offset in halves

    const __half* Asrc = A  + (size_t)(by * 128 + ci) * K + cs8;
    const __half* Bsrc = Bt + (size_t)(bx * 64 + ci) * K + cs8;
    const uint32_t cdst = (uint32_t)(ci * HSTR + cs8) * 2;

    // loop-invariant per-thread ldsm offsets (relative to slot base)
    uint32_t aOff[2], bOff[2];
    #pragma unroll
    for (int mi = 0; mi < 2; mi++)
        aOff[mi] = (uint32_t)((wm * 32 + mi * 16 + l16) * HSTR + lkhi) * 2;
    #pragma unroll
    for (int np = 0; np < 2; np++)
        bOff[np] = (uint32_t)((wn * 32 + np * 16 + l16) * HSTR + lkhi) * 2;

    // prologue: chunk 0 -> slot 0 (A: 4 reps of 32 rows, B: 2 reps)
    #pragma unroll
    for (int rep = 0; rep < 4; rep++)
        cp_async16(sA[0] + cdst + (uint32_t)(rep * 32 * HSTR) * 2,
                   Asrc + (size_t)(rep * 32) * K);
    #pragma unroll
    for (int rep = 0; rep < 2; rep++)
        cp_async16(sB[0] + cdst + (uint32_t)(rep * 32 * HSTR) * 2,
                   Bsrc + (size_t)(rep * 32) * K);
    cp_commit();
    Asrc += HKC; Bsrc += HKC;

    for (int c = 0; c < NC; c++) {
        cp_wait0();
        __syncthreads();

        if (c + 1 < NC) {
            const int slot = (c + 1) & 1;
            #pragma unroll
            for (int rep = 0; rep < 4; rep++)
                cp_async16(sA[slot] + cdst + (uint32_t)(rep * 32 * HSTR) * 2,
                           Asrc + (size_t)(rep * 32) * K);
            #pragma unroll
            for (int rep = 0; rep < 2; rep++)
                cp_async16(sB[slot] + cdst + (uint32_t)(rep * 32 * HSTR) * 2,
                           Bsrc + (size_t)(rep * 32) * K);
            cp_commit();
            Asrc += HKC; Bsrc += HKC;
        }

        const uint32_t sAc = sA[c & 1], sBc = sB[c & 1];
        #pragma unroll
        for (int ks = 0; ks < 4; ks++) {
            const uint32_t ko = (uint32_t)(ks * 16) * 2;
            uint32_t a[2][4];
            #pragma unroll
            for (int mi = 0; mi < 2; mi++)
                ldsm_x4(a[mi][0], a[mi][1], a[mi][2], a[mi][3], sAc + aOff[mi] + ko);
            uint32_t b[4][2];
            #pragma unroll
            for (int np = 0; np < 2; np++)
                ldsm_x4(b[2*np][0], b[2*np+1][0], b[2*np][1], b[2*np+1][1], sBc + bOff[np] + ko);
            #pragma unroll
            for (int ni = 0; ni < 4; ni++)
                #pragma unroll
                for (int mi = 0; mi < 2; mi++)
                    mma_f16(acc[mi][ni][0], acc[mi][ni][1], acc[mi][ni][2], acc[mi][ni][3],
                            a[mi][0], a[mi][1], a[mi][2], a[mi][3], b[ni][0], b[ni][1]);
        }
    }

    if (MODE == 0) {
        #pragma unroll
        for (int mi = 0; mi < 2; mi++) {
            int row = by * 128 + wm * 32 + mi * 16 + lg;
            #pragma unroll
            for (int ni = 0; ni < 4; ni++) {
                int col = bx * 64 + wn * 32 + ni * 8 + (lt << 1);
                *(float2*)(Cf + (size_t)row * N + col)       = make_float2(acc[mi][ni][0], acc[mi][ni][1]);
                *(float2*)(Cf + (size_t)(row + 8) * N + col) = make_float2(acc[mi][ni][2], acc[mi][ni][3]);
            }
        }
    } else {
        // N-tile of 64 = exactly one head: l2-normalize q,k rows (bx<32)
        const bool donorm = (bx < 32);   // bx 0-15: q, 16-31: k, 32-47: v
        __syncthreads();
        float* red = (float*)gsm;        // [2 wn][128 rows]
        float ssl[2], ssh[2];
        #pragma unroll
        for (int mi = 0; mi < 2; mi++) {
            float a = 0.f, h = 0.f;
            #pragma unroll
            for (int ni = 0; ni < 4; ni++) {
                a += acc[mi][ni][0]*acc[mi][ni][0] + acc[mi][ni][1]*acc[mi][ni][1];
                h += acc[mi][ni][2]*acc[mi][ni][2] + acc[mi][ni][3]*acc[mi][ni][3];
            }
            a += __shfl_xor_sync(0xffffffffu, a, 1);
            a += __shfl_xor_sync(0xffffffffu, a, 2);
            h += __shfl_xor_sync(0xffffffffu, h, 1);
            h += __shfl_xor_sync(0xffffffffu, h, 2);
            ssl[mi] = a; ssh[mi] = h;
        }
        if (lt == 0) {
            #pragma unroll
            for (int mi = 0; mi < 2; mi++) {
                int rl = wm * 32 + mi * 16 + lg;
                red[wn * 128 + rl]     = ssl[mi];
                red[wn * 128 + rl + 8] = ssh[mi];
            }
        }
        __syncthreads();
        #pragma unroll
        for (int mi = 0; mi < 2; mi++) {
            int rl = wm * 32 + mi * 16 + lg;
            float il = 1.f, ih = 1.f;
            if (donorm) {
                float tl = ssl[mi] + red[(wn ^ 1) * 128 + rl];
                float th = ssh[mi] + red[(wn ^ 1) * 128 + rl + 8];
                il = 1.0f / fmaxf(sqrtf(tl), 1e-12f);
                ih = 1.0f / fmaxf(sqrtf(th), 1e-12f);
            }
            int row = by * 128 + rl;
            #pragma unroll
            for (int ni = 0; ni < 4; ni++) {
                int col = bx * 64 + wn * 32 + ni * 8 + (lt << 1);
                *(uint32_t*)(Ch + (size_t)row * N + col) =
                    pack_h2(acc[mi][ni][0] * il, acc[mi][ni][1] * il);
                *(uint32_t*)(Ch + (size_t)(row + 8) * N + col) =
                    pack_h2(acc[mi][ni][2] * ih, acc[mi][ni][3] * ih);
            }
        }
    }
}

// ===========================================================================
// Tensor-core flash attention v6 (R12 verbatim — proven): fp16 qkv, cp.async
// double-buffered K/V, register-resident P, ldmatrix.trans V.
// CTA: 128 q rows, 256 threads (8 warps x 16 rows). Key tiles of 64.
// ===========================================================================
#define PH 72

__global__ __launch_bounds__(256) void attn_tc_kernel(
    const __half* __restrict__ qkv, __half* __restrict__ oat)
{
    __shared__ __align__(16) __half Ks[2][64 * PH];
    __shared__ __align__(16) __half Vs[2][64 * PH];

    const int tid  = threadIdx.x;
    const int w    = tid >> 5;
    const int lane = tid & 31;
    const int lg = lane >> 2, lt = lane & 3;
    const int l16  = lane & 15;
    const int lkhi = (lane >> 4) << 3;
    const int qtIdx = gridDim.x - 1 - blockIdx.x;   // long CTAs first
    const int h = blockIdx.y, bb = blockIdx.z;
    const int row0 = qtIdx * 128;
    const size_t rowbase = (size_t)bb * NSEQ;
    const int R0 = row0 + w * 16;

    uint32_t sK[2], sV[2];
    sK[0] = (uint32_t)__cvta_generic_to_shared(&Ks[0][0]);
    sK[1] = (uint32_t)__cvta_generic_to_shared(&Ks[1][0]);
    sV[0] = (uint32_t)__cvta_generic_to_shared(&Vs[0][0]);
    sV[1] = (uint32_t)__cvta_generic_to_shared(&Vs[1][0]);

    // --- Q fragments: fp16 loads, exact x8 scale, resident all kernel ---
    uint32_t aq[4][4];
    {
        const __half2 s8 = __floats2half2_rn(8.0f, 8.0f);
        const __half* q0 = qkv + (rowbase + R0 + lg) * QKVW + h * DHEAD;
        const __half* q1 = q0 + 8 * QKVW;
        #pragma unroll
        for (int ks = 0; ks < 4; ks++) {
            int c = ks * 16 + 2 * lt;
            __half2 v;
            v = __hmul2(*(const __half2*)&q0[c], s8);     aq[ks][0] = *(uint32_t*)&v;
            v = __hmul2(*(const __half2*)&q1[c], s8);     aq[ks][1] = *(uint32_t*)&v;
            v = __hmul2(*(const __half2*)&q0[c + 8], s8); aq[ks][2] = *(uint32_t*)&v;
            v = __hmul2(*(const __half2*)&q1[c + 8], s8); aq[ks][3] = *(uint32_t*)&v;
        }
    }

    float oacc[8][4];
    #pragma unroll
    for (int ni = 0; ni < 8; ni++)
        #pragma unroll
        for (int q = 0; q < 4; q++) oacc[ni][q] = 0.f;
    float m0 = -INFINITY, m1 = -INFINITY, l0 = 0.f, l1 = 0.f;

    const int ntiles = 2 * qtIdx + 2;
    const int ci  = tid >> 3;         // kv row 0..31 (x2 reps)
    const int cs8 = (tid & 7) << 3;   // d-offset in halves

    const __half* kvsrc = qkv + (rowbase + ci) * QKVW + INNER + h * DHEAD + cs8;
    const uint32_t cdst = (uint32_t)(ci * PH + cs8) * 2;

    // prologue: tile 0 -> slot 0
    #pragma unroll
    for (int rep = 0; rep < 2; rep++) {
        const __half* src = kvsrc + (size_t)(rep * 32) * QKVW;
        cp_async16(sK[0] + cdst + (uint32_t)(rep * 32 * PH) * 2, src);
        cp_async16(sV[0] + cdst + (uint32_t)(rep * 32 * PH) * 2, src + INNER);
    }
    cp_commit();
    kvsrc += (size_t)64 * QKVW;

    for (int jt = 0; jt < ntiles; jt++) {
        const int j0 = jt * 64;
        if (jt + 1 < ntiles) {
            const int slot = (jt + 1) & 1;
            #pragma unroll
            for (int rep = 0; rep < 2; rep++) {
                const __half* src = kvsrc + (size_t)(rep * 32) * QKVW;
                cp_async16(sK[slot] + cdst + (uint32_t)(rep * 32 * PH) * 2, src);
                cp_async16(sV[slot] + cdst + (uint32_t)(rep * 32 * PH) * 2, src + INNER);
            }
            kvsrc += (size_t)64 * QKVW;
        }
        cp_commit();
        cp_wait1();
        __syncthreads();

        const int slot = jt & 1;
        if (j0 <= R0 + 15) {
            // --- scores ---
            float sacc[8][4];
            #pragma unroll
            for (int ni = 0; ni < 8; ni++)
                #pragma unroll
                for (int q = 0; q < 4; q++) sacc[ni][q] = 0.f;

            #pragma unroll
            for (int ks = 0; ks < 4; ks++) {
                const uint32_t ko = (uint32_t)(ks * 16) * 2;
                #pragma unroll
                for (int np = 0; np < 4; np++) {
                    uint32_t b0e, b0o, b1e, b1o;
                    ldsm_x4(b0e, b0o, b1e, b1o,
                            sK[slot] + (uint32_t)((np * 16 + l16) * PH + lkhi) * 2 + ko);
                    mma_f16(sacc[2*np][0], sacc[2*np][1], sacc[2*np][2], sacc[2*np][3],
                            aq[ks][0], aq[ks][1], aq[ks][2], aq[ks][3], b0e, b1e);
                    mma_f16(sacc[2*np+1][0], sacc[2*np+1][1], sacc[2*np+1][2], sacc[2*np+1][3],
                            aq[ks][0], aq[ks][1], aq[ks][2], aq[ks][3], b0o, b1o);
                }
            }

            // --- causal mask (diagonal-crossing tiles only) ---
            if (j0 + 63 > R0) {
                int ra = R0 + lg, rb = ra + 8;
                #pragma unroll
                for (int ni = 0; ni < 8; ni++) {
                    int k0c = j0 + ni * 8 + 2 * lt;
                    if (k0c     > ra) sacc[ni][0] = -INFINITY;
                    if (k0c + 1 > ra) sacc[ni][1] = -INFINITY;
                    if (k0c     > rb) sacc[ni][2] = -INFINITY;
                    if (k0c + 1 > rb) sacc[ni][3] = -INFINITY;
                }
            }

            // --- online softmax; pack P into A-fragment registers ---
            float mt0 = -INFINITY, mt1 = -INFINITY;
            #pragma unroll
            for (int ni = 0; ni < 8; ni++) {
                mt0 = fmaxf(mt0, fmaxf(sacc[ni][0], sacc[ni][1]));
                mt1 = fmaxf(mt1, fmaxf(sacc[ni][2], sacc[ni][3]));
            }
            mt0 = fmaxf(mt0, __shfl_xor_sync(0xffffffffu, mt0, 1));
            mt0 = fmaxf(mt0, __shfl_xor_sync(0xffffffffu, mt0, 2));
            mt1 = fmaxf(mt1, __shfl_xor_sync(0xffffffffu, mt1, 1));
            mt1 = fmaxf(mt1, __shfl_xor_sync(0xffffffffu, mt1, 2));
            float mn0 = fmaxf(m0, mt0), mn1 = fmaxf(m1, mt1);
            float c0f = __expf(m0 - mn0), c1f = __expf(m1 - mn1);
            m0 = mn0; m1 = mn1;

            float s0 = 0.f, s1 = 0.f;
            uint32_t pa[4][4];
            #pragma unroll
            for (int ni = 0; ni < 8; ni++) {
                __half2 h01 = __floats2half2_rn(__expf(sacc[ni][0] - m0), __expf(sacc[ni][1] - m0));
                __half2 h23 = __floats2half2_rn(__expf(sacc[ni][2] - m1), __expf(sacc[ni][3] - m1));
                float2 f01 = __half22float2(h01);
                float2 f23 = __half22float2(h23);
                s0 += f01.x + f01.y;
                s1 += f23.x + f23.y;
                int kc = ni >> 1;
                if ((ni & 1) == 0) { pa[kc][0] = *(uint32_t*)&h01; pa[kc][1] = *(uint32_t*)&h23; }
                else               { pa[kc][2] = *(uint32_t*)&h01; pa[kc][3] = *(uint32_t*)&h23; }
            }
            s0 += __shfl_xor_sync(0xffffffffu, s0, 1);
            s0 += __shfl_xor_sync(0xffffffffu, s0, 2);
            s1 += __shfl_xor_sync(0xffffffffu, s1, 1);
            s1 += __shfl_xor_sync(0xffffffffu, s1, 2);
            l0 = l0 * c0f + s0;
            l1 = l1 * c1f + s1;
            #pragma unroll
            for (int ni = 0; ni < 8; ni++) {
                oacc[ni][0] *= c0f; oacc[ni][1] *= c0f;
                oacc[ni][2] *= c1f; oacc[ni][3] *= c1f;
            }

            // --- PV: B from Vs[key][d] via ldmatrix.trans ---
            #pragma unroll
            for (int kc = 0; kc < 4; kc++) {
                #pragma unroll
                for (int np = 0; np < 4; np++) {
                    uint32_t r0, r1, r2, r3;
                    ldsm_x4_t(r0, r1, r2, r3,
                              sV[slot] + (uint32_t)((kc * 16 + l16) * PH + np * 16 + lkhi) * 2);
                    mma_f16(oacc[2*np][0], oacc[2*np][1], oacc[2*np][2], oacc[2*np][3],
                            pa[kc][0], pa[kc][1], pa[kc][2], pa[kc][3], r0, r1);
                    mma_f16(oacc[2*np+1][0], oacc[2*np+1][1], oacc[2*np+1][2], oacc[2*np+1][3],
                            pa[kc][0], pa[kc][1], pa[kc][2], pa[kc][3], r2, r3);
                }
            }
        }
        __syncthreads();   // slot may be overwritten by next iteration's cp.async
    }

    // --- epilogue: normalize, write fp16 [b, n, h*d] ---
    float il0 = 1.0f / l0, il1 = 1.0f / l1;
    __half* outa = oat + (rowbase + R0 + lg) * INNER + h * DHEAD;
    __half* outb = outa + 8 * INNER;
    #pragma unroll
    for (int ni = 0; ni < 8; ni++) {
        int col = ni * 8 + 2 * lt;
        *(uint32_t*)&outa[col] = pack_h2(oacc[ni][0] * il0, oacc[ni][1] * il0);
        *(uint32_t*)&outb[col] = pack_h2(oacc[ni][2] * il1, oacc[ni][3] * il1);
    }
}

// ===========================================================================
extern "C" void kernel_launch(void* const* d_in, const int* in_sizes, int n_in,
                              void* d_out, int out_size)
{
    const float* x    = (const float*)d_in[0];
    const float* lnw  = (const float*)d_in[1];
    const float* lnb  = (const float*)d_in[2];
    const float* Wqkv = (const float*)d_in[3];
    const float* Wout = (const float*)d_in[4];
    float* out = (float*)d_out;

    __half *xn, *qkvh, *oath, *wqkvT, *woutT;
    cudaGetSymbolAddress((void**)&xn,    g_xn_h);
    cudaGetSymbolAddress((void**)&qkvh,  g_qkv_h);
    cudaGetSymbolAddress((void**)&oath,  g_oat_h);
    cudaGetSymbolAddress((void**)&wqkvT, g_wqkvT);
    cudaGetSymbolAddress((void**)&woutT, g_woutT);

    cudaFuncSetAttribute(gemm_fp16_kernel<0>,
                         cudaFuncAttributeMaxDynamicSharedMemorySize, GEMM_SMEM);
    cudaFuncSetAttribute(gemm_fp16_kernel<1>,
                         cudaFuncAttributeMaxDynamicSharedMemorySize, GEMM_SMEM);

    ln_kernel<<<ROWS, 256>>>(x, lnw, lnb, xn);

    transpose_kernel<<<dim3(QKVW / 32, DIM / 32), 256>>>(Wqkv, wqkvT, DIM, QKVW);
    transpose_kernel<<<dim3(INNER / 32, DIM / 32), 256>>>(Wout, woutT, DIM, INNER);

    // QKV projection, fused q/k l2-normalization, fp16 out
    gemm_fp16_kernel<1><<<dim3(QKVW / 64, ROWS / 128), 256, GEMM_SMEM>>>(
        xn, wqkvT, nullptr, qkvh, ROWS, QKVW, DIM);

    attn_tc_kernel<<<dim3(NSEQ / 128, HEADS, BATCH), 256>>>(qkvh, oath);

    gemm_fp16_kernel<0><<<dim3(INNER / 64, ROWS / 128), 256, GEMM_SMEM>>>(
        oath, woutT, out, nullptr, ROWS, INNER, DIM);
}

// round 14
// speedup vs baseline: 1.4220x; 1.0387x over previous
#include <cuda_runtime.h>
#include <cuda_fp16.h>
#include <math.h>
#include <stdint.h>

#define BATCH 2
#define NSEQ  2048
#define DIM   1024
#define HEADS 16
#define DHEAD 64
#define INNER 1024
#define ROWS  (BATCH*NSEQ)   // 4096
#define QKVW  (3*INNER)      // 3072
#define LN_EPS 1e-5f

// Scratch (static device allocations — allowed)
__device__ __half g_xn_h  [(size_t)ROWS * DIM  ];
__device__ __half g_qkv_h [(size_t)ROWS * QKVW ];
__device__ __half g_oat_h [(size_t)ROWS * INNER];
__device__ __half g_wqkvh [(size_t)DIM * QKVW ];   // row-major [K, N] fp16
__device__ __half g_wouth [(size_t)INNER * DIM ];  // row-major [K, N] fp16

// ===========================================================================
// helpers
// ===========================================================================
__device__ __forceinline__ void mma_f16(
    float& c0, float& c1, float& c2, float& c3,
    uint32_t a0, uint32_t a1, uint32_t a2, uint32_t a3,
    uint32_t b0, uint32_t b1)
{
    asm volatile(
        "mma.sync.aligned.m16n8k16.row.col.f32.f16.f16.f32 "
        "{%0,%1,%2,%3}, {%4,%5,%6,%7}, {%8,%9}, {%0,%1,%2,%3};"
        : "+f"(c0), "+f"(c1), "+f"(c2), "+f"(c3)
        : "r"(a0), "r"(a1), "r"(a2), "r"(a3), "r"(b0), "r"(b1));
}
__device__ __forceinline__ void ldsm_x4(
    uint32_t& r0, uint32_t& r1, uint32_t& r2, uint32_t& r3, uint32_t addr)
{
    asm volatile("ldmatrix.sync.aligned.m8n8.x4.shared.b16 {%0,%1,%2,%3}, [%4];"
                 : "=r"(r0), "=r"(r1), "=r"(r2), "=r"(r3) : "r"(addr));
}
__device__ __forceinline__ void ldsm_x4_t(
    uint32_t& r0, uint32_t& r1, uint32_t& r2, uint32_t& r3, uint32_t addr)
{
    asm volatile("ldmatrix.sync.aligned.m8n8.x4.trans.shared.b16 {%0,%1,%2,%3}, [%4];"
                 : "=r"(r0), "=r"(r1), "=r"(r2), "=r"(r3) : "r"(addr));
}
__device__ __forceinline__ uint32_t pack_h2(float a, float b) {
    __half2 h = __floats2half2_rn(a, b);
    return *(uint32_t*)&h;
}
__device__ __forceinline__ void cp_async16(uint32_t dst, const void* src) {
    asm volatile("cp.async.cg.shared.global [%0], [%1], 16;" :: "r"(dst), "l"(src));
}
__device__ __forceinline__ void cp_commit() {
    asm volatile("cp.async.commit_group;" ::: "memory");
}
__device__ __forceinline__ void cp_wait0() {
    asm volatile("cp.async.wait_group 0;" ::: "memory");
}
__device__ __forceinline__ void cp_wait1() {
    asm volatile("cp.async.wait_group 1;" ::: "memory");
}

// ===========================================================================
// fp32 -> fp16 elementwise convert (weights), float4-vectorized
// ===========================================================================
__global__ __launch_bounds__(256) void cvt_kernel(
    const float* __restrict__ in, __half* __restrict__ out, int n4)
{
    int i = blockIdx.x * blockDim.x + threadIdx.x;
    if (i < n4) {
        float4 v = ((const float4*)in)[i];
        uint2 o;
        o.x = pack_h2(v.x, v.y);
        o.y = pack_h2(v.z, v.w);
        ((uint2*)out)[i] = o;
    }
}

// ===========================================================================
// LayerNorm: one block (256 thr) per row of 1024. fp16 out.
// ===========================================================================
__global__ __launch_bounds__(256) void ln_kernel(
    const float* __restrict__ x, const float* __restrict__ w,
    const float* __restrict__ b, __half* __restrict__ out)
{
    int row = blockIdx.x;
    int tid = threadIdx.x;
    const float4 v = ((const float4*)(x + (size_t)row * DIM))[tid];
    float s  = v.x + v.y + v.z + v.w;
    float ss = v.x*v.x + v.y*v.y + v.z*v.z + v.w*v.w;
    #pragma unroll
    for (int o = 16; o; o >>= 1) {
        s  += __shfl_xor_sync(0xffffffffu, s,  o);
        ss += __shfl_xor_sync(0xffffffffu, ss, o);
    }
    __shared__ float sh_s[8], sh_ss[8];
    int wid = tid >> 5, lane = tid & 31;
    if (lane == 0) { sh_s[wid] = s; sh_ss[wid] = ss; }
    __syncthreads();
    if (tid == 0) {
        float a = 0.f, q = 0.f;
        #pragma unroll
        for (int i = 0; i < 8; i++) { a += sh_s[i]; q += sh_ss[i]; }
        sh_s[0] = a; sh_ss[0] = q;
    }
    __syncthreads();
    float mu   = sh_s[0]  * (1.0f / DIM);
    float var  = sh_ss[0] * (1.0f / DIM) - mu * mu;
    float rstd = rsqrtf(var + LN_EPS);
    float4 w4 = ((const float4*)w)[tid];
    float4 b4 = ((const float4*)b)[tid];
    uint2 o2;
    o2.x = pack_h2((v.x - mu) * rstd * w4.x + b4.x,
                   (v.y - mu) * rstd * w4.y + b4.y);
    o2.y = pack_h2((v.z - mu) * rstd * w4.z + b4.z,
                   (v.w - mu) * rstd * w4.w + b4.w);
    ((uint2*)(out + (size_t)row * DIM))[tid] = o2;
}

// ===========================================================================
// fp16 mma GEMM v8: B ROW-MAJOR [K, N] via ldmatrix.trans (no weight
// transpose kernel needed). CTA tile 128x64, BK=64, dynamic smem 55296 B,
// 3 CTAs/SM. 256 threads, 8 warps 4m x 2n, warp tile 32x32.
// MODE 0: C fp32. MODE 1: C fp16 + fused q/k l2norm (bx<32; one head/tile).
// ===========================================================================
#define HKC 64
#define HSTR 72
#define GEMM_SMEM ((2*128 + 2*64) * HSTR * 2)   // 55296 B

template<int MODE>
__global__ __launch_bounds__(256, 3) void gemm_fp16_kernel(
    const __half* __restrict__ A, const __half* __restrict__ B,
    float* __restrict__ Cf, __half* __restrict__ Ch, int M, int N, int K)
{
    extern __shared__ __align__(16) __half gsm[];

    const int tid  = threadIdx.x;
    const int wid  = tid >> 5;
    const int lane = tid & 31;
    const int bx = blockIdx.x, by = blockIdx.y;
    const int wm = wid & 3;           // 0..3 (m)
    const int wn = wid >> 2;          // 0..1 (n)
    const int lg = lane >> 2;
    const int lt = lane & 3;
    const int l16  = lane & 15;
    const int lkhi = (lane >> 4) << 3;

    uint32_t sA[2], sB[2];
    sA[0] = (uint32_t)__cvta_generic_to_shared(gsm);
    sA[1] = sA[0] + 128 * HSTR * 2;
    sB[0] = sA[0] + 2 * 128 * HSTR * 2;
    sB[1] = sB[0] + 64 * HSTR * 2;

    float acc[2][4][4];
    #pragma unroll
    for (int i = 0; i < 2; i++)
        #pragma unroll
        for (int j = 0; j < 4; j++)
            #pragma unroll
            for (int q = 0; q < 4; q++) acc[i][j][q] = 0.f;

    const int NC = K / HKC;                 // 16
    // A copy: row = tid>>3 (+32*rep), col segment (tid&7)*8 halves
    const int ci   = tid >> 3;
    const int cs8  = (tid & 7) << 3;
    // B copy: k-row = tid>>2 (0..63), n segment (tid&3)*8 halves (+32*rep)
    const int cbr  = tid >> 2;
    const int cbc  = (tid & 3) << 3;

    const __half* Asrc = A + (size_t)(by * 128 + ci) * K + cs8;
    const __half* Bsrc = B + (size_t)cbr * N + bx * 64 + cbc;
    const uint32_t cdstA = (uint32_t)(ci * HSTR + cs8) * 2;
    const uint32_t cdstB = (uint32_t)(cbr * HSTR + cbc) * 2;

    // loop-invariant per-thread ldsm offsets (relative to slot base)
    uint32_t aOff[2], bOff[2];
    #pragma unroll
    for (int mi = 0; mi < 2; mi++)
        aOff[mi] = (uint32_t)((wm * 32 + mi * 16 + l16) * HSTR + lkhi) * 2;
    #pragma unroll
    for (int np = 0; np < 2; np++)
        bOff[np] = (uint32_t)(l16 * HSTR + wn * 32 + np * 16 + lkhi) * 2;

    // prologue: chunk 0 -> slot 0
    #pragma unroll
    for (int rep = 0; rep < 4; rep++)
        cp_async16(sA[0] + cdstA + (uint32_t)(rep * 32 * HSTR) * 2,
                   Asrc + (size_t)(rep * 32) * K);
    #pragma unroll
    for (int rep = 0; rep < 2; rep++)
        cp_async16(sB[0] + cdstB + (uint32_t)(rep * 32) * 2,
                   Bsrc + rep * 32);
    cp_commit();
    Asrc += HKC;
    Bsrc += (size_t)HKC * N;

    for (int c = 0; c < NC; c++) {
        cp_wait0();
        __syncthreads();

        if (c + 1 < NC) {
            const int slot = (c + 1) & 1;
            #pragma unroll
            for (int rep = 0; rep < 4; rep++)
                cp_async16(sA[slot] + cdstA + (uint32_t)(rep * 32 * HSTR) * 2,
                           Asrc + (size_t)(rep * 32) * K);
            #pragma unroll
            for (int rep = 0; rep < 2; rep++)
                cp_async16(sB[slot] + cdstB + (uint32_t)(rep * 32) * 2,
                           Bsrc + rep * 32);
            cp_commit();
            Asrc += HKC;
            Bsrc += (size_t)HKC * N;
        }

        const uint32_t sAc = sA[c & 1], sBc = sB[c & 1];
        #pragma unroll
        for (int ks = 0; ks < 4; ks++) {
            const uint32_t koA = (uint32_t)(ks * 16) * 2;
            const uint32_t koB = (uint32_t)(ks * 16 * HSTR) * 2;
            uint32_t a[2][4];
            #pragma unroll
            for (int mi = 0; mi < 2; mi++)
                ldsm_x4(a[mi][0], a[mi][1], a[mi][2], a[mi][3], sAc + aOff[mi] + koA);
            uint32_t b[4][2];
            #pragma unroll
            for (int np = 0; np < 2; np++)
                ldsm_x4_t(b[2*np][0], b[2*np][1], b[2*np+1][0], b[2*np+1][1],
                          sBc + bOff[np] + koB);
            #pragma unroll
            for (int ni = 0; ni < 4; ni++)
                #pragma unroll
                for (int mi = 0; mi < 2; mi++)
                    mma_f16(acc[mi][ni][0], acc[mi][ni][1], acc[mi][ni][2], acc[mi][ni][3],
                            a[mi][0], a[mi][1], a[mi][2], a[mi][3], b[ni][0], b[ni][1]);
        }
    }

    if (MODE == 0) {
        #pragma unroll
        for (int mi = 0; mi < 2; mi++) {
            int row = by * 128 + wm * 32 + mi * 16 + lg;
            #pragma unroll
            for (int ni = 0; ni < 4; ni++) {
                int col = bx * 64 + wn * 32 + ni * 8 + (lt << 1);
                *(float2*)(Cf + (size_t)row * N + col)       = make_float2(acc[mi][ni][0], acc[mi][ni][1]);
                *(float2*)(Cf + (size_t)(row + 8) * N + col) = make_float2(acc[mi][ni][2], acc[mi][ni][3]);
            }
        }
    } else {
        // N-tile of 64 = exactly one head: l2-normalize q,k rows (bx<32)
        const bool donorm = (bx < 32);   // bx 0-15: q, 16-31: k, 32-47: v
        __syncthreads();
        float* red = (float*)gsm;        // [2 wn][128 rows]
        float ssl[2], ssh[2];
        #pragma unroll
        for (int mi = 0; mi < 2; mi++) {
            float a = 0.f, h = 0.f;
            #pragma unroll
            for (int ni = 0; ni < 4; ni++) {
                a += acc[mi][ni][0]*acc[mi][ni][0] + acc[mi][ni][1]*acc[mi][ni][1];
                h += acc[mi][ni][2]*acc[mi][ni][2] + acc[mi][ni][3]*acc[mi][ni][3];
            }
            a += __shfl_xor_sync(0xffffffffu, a, 1);
            a += __shfl_xor_sync(0xffffffffu, a, 2);
            h += __shfl_xor_sync(0xffffffffu, h, 1);
            h += __shfl_xor_sync(0xffffffffu, h, 2);
            ssl[mi] = a; ssh[mi] = h;
        }
        if (lt == 0) {
            #pragma unroll
            for (int mi = 0; mi < 2; mi++) {
                int rl = wm * 32 + mi * 16 + lg;
                red[wn * 128 + rl]     = ssl[mi];
                red[wn * 128 + rl + 8] = ssh[mi];
            }
        }
        __syncthreads();
        #pragma unroll
        for (int mi = 0; mi < 2; mi++) {
            int rl = wm * 32 + mi * 16 + lg;
            float il = 1.f, ih = 1.f;
            if (donorm) {
                float tl = ssl[mi] + red[(wn ^ 1) * 128 + rl];
                float th = ssh[mi] + red[(wn ^ 1) * 128 + rl + 8];
                il = 1.0f / fmaxf(sqrtf(tl), 1e-12f);
                ih = 1.0f / fmaxf(sqrtf(th), 1e-12f);
            }
            int row = by * 128 + rl;
            #pragma unroll
            for (int ni = 0; ni < 4; ni++) {
                int col = bx * 64 + wn * 32 + ni * 8 + (lt << 1);
                *(uint32_t*)(Ch + (size_t)row * N + col) =
                    pack_h2(acc[mi][ni][0] * il, acc[mi][ni][1] * il);
                *(uint32_t*)(Ch + (size_t)(row + 8) * N + col) =
                    pack_h2(acc[mi][ni][2] * ih, acc[mi][ni][3] * ih);
            }
        }
    }
}

// ===========================================================================
// Tensor-core flash attention (R12 math, now __launch_bounds__(256,2) for
// 2 CTAs/SM): fp16 qkv, cp.async double-buffered K/V, register-resident P,
// ldmatrix.trans V. CTA: 128 q rows, 8 warps x 16 rows. Key tiles of 64.
// ===========================================================================
#define PH 72

__global__ __launch_bounds__(256, 2) void attn_tc_kernel(
    const __half* __restrict__ qkv, __half* __restrict__ oat)
{
    __shared__ __align__(16) __half Ks[2][64 * PH];
    __shared__ __align__(16) __half Vs[2][64 * PH];

    const int tid  = threadIdx.x;
    const int w    = tid >> 5;
    const int lane = tid & 31;
    const int lg = lane >> 2, lt = lane & 3;
    const int l16  = lane & 15;
    const int lkhi = (lane >> 4) << 3;
    const int qtIdx = gridDim.x - 1 - blockIdx.x;   // long CTAs first
    const int h = blockIdx.y, bb = blockIdx.z;
    const int row0 = qtIdx * 128;
    const size_t rowbase = (size_t)bb * NSEQ;
    const int R0 = row0 + w * 16;

    uint32_t sK[2], sV[2];
    sK[0] = (uint32_t)__cvta_generic_to_shared(&Ks[0][0]);
    sK[1] = (uint32_t)__cvta_generic_to_shared(&Ks[1][0]);
    sV[0] = (uint32_t)__cvta_generic_to_shared(&Vs[0][0]);
    sV[1] = (uint32_t)__cvta_generic_to_shared(&Vs[1][0]);

    // --- Q fragments: fp16 loads, exact x8 scale, resident all kernel ---
    uint32_t aq[4][4];
    {
        const __half2 s8 = __floats2half2_rn(8.0f, 8.0f);
        const __half* q0 = qkv + (rowbase + R0 + lg) * QKVW + h * DHEAD;
        const __half* q1 = q0 + 8 * QKVW;
        #pragma unroll
        for (int ks = 0; ks < 4; ks++) {
            int c = ks * 16 + 2 * lt;
            __half2 v;
            v = __hmul2(*(const __half2*)&q0[c], s8);     aq[ks][0] = *(uint32_t*)&v;
            v = __hmul2(*(const __half2*)&q1[c], s8);     aq[ks][1] = *(uint32_t*)&v;
            v = __hmul2(*(const __half2*)&q0[c + 8], s8); aq[ks][2] = *(uint32_t*)&v;
            v = __hmul2(*(const __half2*)&q1[c + 8], s8); aq[ks][3] = *(uint32_t*)&v;
        }
    }

    float oacc[8][4];
    #pragma unroll
    for (int ni = 0; ni < 8; ni++)
        #pragma unroll
        for (int q = 0; q < 4; q++) oacc[ni][q] = 0.f;
    float m0 = -INFINITY, m1 = -INFINITY, l0 = 0.f, l1 = 0.f;

    const int ntiles = 2 * qtIdx + 2;
    const int ci  = tid >> 3;         // kv row 0..31 (x2 reps)
    const int cs8 = (tid & 7) << 3;   // d-offset in halves

    const __half* kvsrc = qkv + (rowbase + ci) * QKVW + INNER + h * DHEAD + cs8;
    const uint32_t cdst = (uint32_t)(ci * PH + cs8) * 2;

    // prologue: tile 0 -> slot 0
    #pragma unroll
    for (int rep = 0; rep < 2; rep++) {
        const __half* src = kvsrc + (size_t)(rep * 32) * QKVW;
        cp_async16(sK[0] + cdst + (uint32_t)(rep * 32 * PH) * 2, src);
        cp_async16(sV[0] + cdst + (uint32_t)(rep * 32 * PH) * 2, src + INNER);
    }
    cp_commit();
    kvsrc += (size_t)64 * QKVW;

    for (int jt = 0; jt < ntiles; jt++) {
        const int j0 = jt * 64;
        if (jt + 1 < ntiles) {
            const int slot = (jt + 1) & 1;
            #pragma unroll
            for (int rep = 0; rep < 2; rep++) {
                const __half* src = kvsrc + (size_t)(rep * 32) * QKVW;
                cp_async16(sK[slot] + cdst + (uint32_t)(rep * 32 * PH) * 2, src);
                cp_async16(sV[slot] + cdst + (uint32_t)(rep * 32 * PH) * 2, src + INNER);
            }
            kvsrc += (size_t)64 * QKVW;
        }
        cp_commit();
        cp_wait1();
        __syncthreads();

        const int slot = jt & 1;
        if (j0 <= R0 + 15) {
            // --- scores ---
            float sacc[8][4];
            #pragma unroll
            for (int ni = 0; ni < 8; ni++)
                #pragma unroll
                for (int q = 0; q < 4; q++) sacc[ni][q] = 0.f;

            #pragma unroll
            for (int ks = 0; ks < 4; ks++) {
                const uint32_t ko = (uint32_t)(ks * 16) * 2;
                #pragma unroll
                for (int np = 0; np < 4; np++) {
                    uint32_t b0e, b0o, b1e, b1o;
                    ldsm_x4(b0e, b0o, b1e, b1o,
                            sK[slot] + (uint32_t)((np * 16 + l16) * PH + lkhi) * 2 + ko);
                    mma_f16(sacc[2*np][0], sacc[2*np][1], sacc[2*np][2], sacc[2*np][3],
                            aq[ks][0], aq[ks][1], aq[ks][2], aq[ks][3], b0e, b1e);
                    mma_f16(sacc[2*np+1][0], sacc[2*np+1][1], sacc[2*np+1][2], sacc[2*np+1][3],
                            aq[ks][0], aq[ks][1], aq[ks][2], aq[ks][3], b0o, b1o);
                }
            }

            // --- causal mask (diagonal-crossing tiles only) ---
            if (j0 + 63 > R0) {
                int ra = R0 + lg, rb = ra + 8;
                #pragma unroll
                for (int ni = 0; ni < 8; ni++) {
                    int k0c = j0 + ni * 8 + 2 * lt;
                    if (k0c     > ra) sacc[ni][0] = -INFINITY;
                    if (k0c + 1 > ra) sacc[ni][1] = -INFINITY;
                    if (k0c     > rb) sacc[ni][2] = -INFINITY;
                    if (k0c + 1 > rb) sacc[ni][3] = -INFINITY;
                }
            }

            // --- online softmax; pack P into A-fragment registers ---
            float mt0 = -INFINITY, mt1 = -INFINITY;
            #pragma unroll
            for (int ni = 0; ni < 8; ni++) {
                mt0 = fmaxf(mt0, fmaxf(sacc[ni][0], sacc[ni][1]));
                mt1 = fmaxf(mt1, fmaxf(sacc[ni][2], sacc[ni][3]));
            }
            mt0 = fmaxf(mt0, __shfl_xor_sync(0xffffffffu, mt0, 1));
            mt0 = fmaxf(mt0, __shfl_xor_sync(0xffffffffu, mt0, 2));
            mt1 = fmaxf(mt1, __shfl_xor_sync(0xffffffffu, mt1, 1));
            mt1 = fmaxf(mt1, __shfl_xor_sync(0xffffffffu, mt1, 2));
            float mn0 = fmaxf(m0, mt0), mn1 = fmaxf(m1, mt1);
            float c0f = __expf(m0 - mn0), c1f = __expf(m1 - mn1);
            m0 = mn0; m1 = mn1;

            float s0 = 0.f, s1 = 0.f;
            uint32_t pa[4][4];
            #pragma unroll
            for (int ni = 0; ni < 8; ni++) {
                __half2 h01 = __floats2half2_rn(__expf(sacc[ni][0] - m0), __expf(sacc[ni][1] - m0));
                __half2 h23 = __floats2half2_rn(__expf(sacc[ni][2] - m1), __expf(sacc[ni][3] - m1));
                float2 f01 = __half22float2(h01);
                float2 f23 = __half22float2(h23);
                s0 += f01.x + f01.y;
                s1 += f23.x + f23.y;
                int kc = ni >> 1;
                if ((ni & 1) == 0) { pa[kc][0] = *(uint32_t*)&h01; pa[kc][1] = *(uint32_t*)&h23; }
                else               { pa[kc][2] = *(uint32_t*)&h01; pa[kc][3] = *(uint32_t*)&h23; }
            }
            s0 += __shfl_xor_sync(0xffffffffu, s0, 1);
            s0 += __shfl_xor_sync(0xffffffffu, s0, 2);
            s1 += __shfl_xor_sync(0xffffffffu, s1, 1);
            s1 += __shfl_xor_sync(0xffffffffu, s1, 2);
            l0 = l0 * c0f + s0;
            l1 = l1 * c1f + s1;
            #pragma unroll
            for (int ni = 0; ni < 8; ni++) {
                oacc[ni][0] *= c0f; oacc[ni][1] *= c0f;
                oacc[ni][2] *= c1f; oacc[ni][3] *= c1f;
            }

            // --- PV: B from Vs[key][d] via ldmatrix.trans ---
            #pragma unroll
            for (int kc = 0; kc < 4; kc++) {
                #pragma unroll
                for (int np = 0; np < 4; np++) {
                    uint32_t r0, r1, r2, r3;
                    ldsm_x4_t(r0, r1, r2, r3,
                              sV[slot] + (uint32_t)((kc * 16 + l16) * PH + np * 16 + lkhi) * 2);
                    mma_f16(oacc[2*np][0], oacc[2*np][1], oacc[2*np][2], oacc[2*np][3],
                            pa[kc][0], pa[kc][1], pa[kc][2], pa[kc][3], r0, r1);
                    mma_f16(oacc[2*np+1][0], oacc[2*np+1][1], oacc[2*np+1][2], oacc[2*np+1][3],
                            pa[kc][0], pa[kc][1], pa[kc][2], pa[kc][3], r2, r3);
                }
            }
        }
        __syncthreads();   // slot may be overwritten by next iteration's cp.async
    }

    // --- epilogue: normalize, write fp16 [b, n, h*d] ---
    float il0 = 1.0f / l0, il1 = 1.0f / l1;
    __half* outa = oat + (rowbase + R0 + lg) * INNER + h * DHEAD;
    __half* outb = outa + 8 * INNER;
    #pragma unroll
    for (int ni = 0; ni < 8; ni++) {
        int col = ni * 8 + 2 * lt;
        *(uint32_t*)&outa[col] = pack_h2(oacc[ni][0] * il0, oacc[ni][1] * il0);
        *(uint32_t*)&outb[col] = pack_h2(oacc[ni][2] * il1, oacc[ni][3] * il1);
    }
}

// ===========================================================================
extern "C" void kernel_launch(void* const* d_in, const int* in_sizes, int n_in,
                              void* d_out, int out_size)
{
    const float* x    = (const float*)d_in[0];
    const float* lnw  = (const float*)d_in[1];
    const float* lnb  = (const float*)d_in[2];
    const float* Wqkv = (const float*)d_in[3];
    const float* Wout = (const float*)d_in[4];
    float* out = (float*)d_out;

    __half *xn, *qkvh, *oath, *wqkvh, *wouth;
    cudaGetSymbolAddress((void**)&xn,    g_xn_h);
    cudaGetSymbolAddress((void**)&qkvh,  g_qkv_h);
    cudaGetSymbolAddress((void**)&oath,  g_oat_h);
    cudaGetSymbolAddress((void**)&wqkvh, g_wqkvh);
    cudaGetSymbolAddress((void**)&wouth, g_wouth);

    cudaFuncSetAttribute(gemm_fp16_kernel<0>,
                         cudaFuncAttributeMaxDynamicSharedMemorySize, GEMM_SMEM);
    cudaFuncSetAttribute(gemm_fp16_kernel<1>,
                         cudaFuncAttributeMaxDynamicSharedMemorySize, GEMM_SMEM);

    ln_kernel<<<ROWS, 256>>>(x, lnw, lnb, xn);

    // fp32 -> fp16 weight converts (row-major preserved; no transpose)
    cvt_kernel<<<(DIM * QKVW / 4 + 255) / 256, 256>>>(Wqkv, wqkvh, DIM * QKVW / 4);
    cvt_kernel<<<(INNER * DIM / 4 + 255) / 256, 256>>>(Wout, wouth, INNER * DIM / 4);

    // QKV projection, fused q/k l2-normalization, fp16 out
    gemm_fp16_kernel<1><<<dim3(QKVW / 64, ROWS / 128), 256, GEMM_SMEM>>>(
        xn, wqkvh, nullptr, qkvh, ROWS, QKVW, DIM);

    attn_tc_kernel<<<dim3(NSEQ / 128, HEADS, BATCH), 256>>>(qkvh, oath);

    gemm_fp16_kernel<0><<<dim3(INNER / 64, ROWS / 128), 256, GEMM_SMEM>>>(
        oath, wouth, out, nullptr, ROWS, INNER, DIM);
}